// round 5
// baseline (speedup 1.0000x reference)
#include <cuda_runtime.h>
#include <cuda_bf16.h>
#include <cuda_fp16.h>
#include <math.h>
#include <stdint.h>

// Problem constants
#define B_  32
#define T_  512
#define C_  512
#define TD_ 256
#define G_  3
#define MROWS (B_ * C_)        // 16384 (== B_*T_)
#define KF  (512 * 6)          // 3072 expanded-feature K
#define KCH 6144               // ch KAN concatenated K' = 2*KF
#define KCL 2048               // ch linear concatenated K' = 2*1024
#define NTOK 8388608           // B*T*C

// GEMM tiling (both kernels): CTA 128x256, BK=64
#define MT 128
#define NT 256
#define BK 64

// bf16x3 kernel smem: per buffer Ah 16K | Al 16K | Bh 32K | Bl 32K = 96K, x2
#define OFF_AL 16384u
#define OFF_BH 32768u
#define OFF_BL 65536u
#define BUF_STRIDE 98304u
#define SMEM3_SZ (2 * 98304)

// std fp16 kernel smem: per buffer A 16K | B 32K = 48K, 4 stages
#define SOFF_B 16384u
#define SBUF 49152u
#define SMEMS_SZ (4 * 49152)

#define STG_S 261              // epilogue stage row stride (floats)

// ----------------------------------------------------------------------------
// Scratch arena (single device global, stage-aliased)
// ----------------------------------------------------------------------------
#define MB (1024ull * 1024ull)
#define OFF_FEAT    0ull              // tok: Fh(96MB)@0, Fl(96MB)@96MB | ch: F16(192MB)@0
#define OFF_TOKFL   (96ull  * MB)
#define OFF_Z       (192ull * MB)     // tok: Zh(8MB)@192, Zl(8MB)@200 | ch: Z216(64MB)@192
#define OFF_TOKZL   (200ull * MB)
#define OFF_TBH     (256ull * MB)     // tok coef hi (1.5MB)
#define OFF_TBL     (258ull * MB)     // tok coef lo
#define OFF_TWH     (260ull * MB)     // tok lw hi (0.25MB)
#define OFF_TWL     (262ull * MB)     // tok lw lo
#define OFF_C16     (264ull * MB)     // ch coef fp16 dup (12MB)
#define OFF_W16     (276ull * MB)     // ch lw fp16 dup (2MB)
#define OFF_LN      (278ull * MB)     // fp32 LN buf (32MB)
#define OFF_X1      (310ull * MB)     // fp32 x1 (32MB)
#define SCRATCH_SZ  (342ull * MB)
__device__ __align__(256) char g_scratch[SCRATCH_SZ];

// ----------------------------------------------------------------------------
// PTX helpers
// ----------------------------------------------------------------------------
__device__ __forceinline__ uint32_t smem_u32(const void* p) {
    uint32_t a;
    asm("{ .reg .u64 t; cvta.to.shared.u64 t, %1; cvt.u32.u64 %0, t; }" : "=r"(a) : "l"(p));
    return a;
}
__device__ __forceinline__ void cpasync16(uint32_t dst, const void* src) {
    asm volatile("cp.async.cg.shared.global [%0], [%1], 16;" :: "r"(dst), "l"(src));
}
__device__ __forceinline__ void cp_commit() {
    asm volatile("cp.async.commit_group;" ::: "memory");
}
__device__ __forceinline__ void cp_wait0() {
    asm volatile("cp.async.wait_group 0;" ::: "memory");
}
__device__ __forceinline__ void cp_wait1() {
    asm volatile("cp.async.wait_group 1;" ::: "memory");
}
__device__ __forceinline__ void cp_wait2() {
    asm volatile("cp.async.wait_group 2;" ::: "memory");
}
__device__ __forceinline__ void ldsm4(uint32_t addr, uint32_t r[4]) {
    asm volatile("ldmatrix.sync.aligned.m8n8.x4.shared.b16 {%0,%1,%2,%3}, [%4];"
                 : "=r"(r[0]), "=r"(r[1]), "=r"(r[2]), "=r"(r[3]) : "r"(addr));
}
__device__ __forceinline__ void mma_bf16(float d[4], const uint32_t a[4], const uint32_t b[2]) {
    asm volatile(
        "mma.sync.aligned.m16n8k16.row.col.f32.bf16.bf16.f32 "
        "{%0,%1,%2,%3}, {%4,%5,%6,%7}, {%8,%9}, {%0,%1,%2,%3};"
        : "+f"(d[0]), "+f"(d[1]), "+f"(d[2]), "+f"(d[3])
        : "r"(a[0]), "r"(a[1]), "r"(a[2]), "r"(a[3]), "r"(b[0]), "r"(b[1]));
}
__device__ __forceinline__ void mma_f16(float d[4], const uint32_t a[4], const uint32_t b[2]) {
    asm volatile(
        "mma.sync.aligned.m16n8k16.row.col.f32.f16.f16.f32 "
        "{%0,%1,%2,%3}, {%4,%5,%6,%7}, {%8,%9}, {%0,%1,%2,%3};"
        : "+f"(d[0]), "+f"(d[1]), "+f"(d[2]), "+f"(d[3])
        : "r"(a[0]), "r"(a[1]), "r"(a[2]), "r"(a[3]), "r"(b[0]), "r"(b[1]));
}
__device__ __forceinline__ void split_bf(float v, __nv_bfloat16& h, __nv_bfloat16& l) {
    h = __float2bfloat16(v);
    l = __float2bfloat16(v - __bfloat162float(h));
}
__device__ __forceinline__ void split_h(float v, __half& h, __half& l) {
    h = __float2half_rn(v);
    l = __float2half_rn(v - __half2float(h));
}

// ----------------------------------------------------------------------------
// LayerNorm (stage 1 only): one block per row of 512, 256 threads
// ----------------------------------------------------------------------------
__global__ void ln_kernel(const float* __restrict__ x,
                          const float* __restrict__ w,
                          const float* __restrict__ b,
                          float* __restrict__ out)
{
    int row = blockIdx.x;
    const float2* xr = (const float2*)(x + (size_t)row * C_);
    float2 v = xr[threadIdx.x];
    float s  = v.x + v.y;
    float sq = v.x * v.x + v.y * v.y;

    __shared__ float ss[8], sqq[8];
    __shared__ float s_mean, s_rstd;
    #pragma unroll
    for (int o = 16; o > 0; o >>= 1) {
        s  += __shfl_down_sync(0xffffffffu, s,  o);
        sq += __shfl_down_sync(0xffffffffu, sq, o);
    }
    int lane = threadIdx.x & 31, wid = threadIdx.x >> 5;
    if (lane == 0) { ss[wid] = s; sqq[wid] = sq; }
    __syncthreads();
    if (wid == 0) {
        float a = (lane < 8) ? ss[lane]  : 0.f;
        float q = (lane < 8) ? sqq[lane] : 0.f;
        #pragma unroll
        for (int o = 4; o > 0; o >>= 1) {
            a += __shfl_down_sync(0xffffffffu, a, o);
            q += __shfl_down_sync(0xffffffffu, q, o);
        }
        if (lane == 0) {
            float m = a * (1.0f / C_);
            float var = q * (1.0f / C_) - m * m;
            s_mean = m;
            s_rstd = rsqrtf(var + 1e-5f);
        }
    }
    __syncthreads();
    float m = s_mean, r = s_rstd;
    float2 wv = ((const float2*)w)[threadIdx.x];
    float2 bv = ((const float2*)b)[threadIdx.x];
    float2 ov;
    ov.x = (v.x - m) * r * wv.x + bv.x;
    ov.y = (v.y - m) * r * wv.y + bv.y;
    ((float2*)(out + (size_t)row * C_))[threadIdx.x] = ov;
}

// ----------------------------------------------------------------------------
// Pack tok coef (2, 256, 512, 3) -> bf16 hi/lo (256 x KF)
// ----------------------------------------------------------------------------
__global__ void pack_coef3(const float* __restrict__ coef,
                           __nv_bfloat16* __restrict__ Bh,
                           __nv_bfloat16* __restrict__ Bl, int O)
{
    int total = O * KF;
    int idx = blockIdx.x * blockDim.x + threadIdx.x;
    if (idx >= total) return;
    int o    = idx / KF;
    int r    = idx % KF;
    int i    = r / 6;
    int rr   = r % 6;
    int g    = rr >> 1;
    int trig = rr & 1;
    float v = coef[(((size_t)trig * O + o) * 512 + i) * G_ + g];
    split_bf(v, Bh[idx], Bl[idx]);
}

// Pack tok lw -> bf16 hi/lo
__global__ void pack_w3(const float* __restrict__ w,
                        __nv_bfloat16* __restrict__ Wh,
                        __nv_bfloat16* __restrict__ Wl, int total)
{
    int idx = blockIdx.x * blockDim.x + threadIdx.x;
    if (idx >= total) return;
    split_bf(w[idx], Wh[idx], Wl[idx]);
}

// Pack ch coef (2, 1024, 512, 3) -> fp16 duplicated (1024 x 6144): [C16|C16]
__global__ void pack_coef16(const float* __restrict__ coef,
                            __half* __restrict__ out, int O)
{
    int total = O * KF;
    int idx = blockIdx.x * blockDim.x + threadIdx.x;
    if (idx >= total) return;
    int o    = idx / KF;
    int r    = idx % KF;
    int i    = r / 6;
    int rr   = r % 6;
    int g    = rr >> 1;
    int trig = rr & 1;
    __half h = __float2half_rn(coef[(((size_t)trig * O + o) * 512 + i) * G_ + g]);
    out[(size_t)o * KCH + r]      = h;
    out[(size_t)o * KCH + KF + r] = h;
}

// Pack ch lw (512 x 1024) -> fp16 duplicated (512 x 2048): [W16|W16]
__global__ void pack_w16(const float* __restrict__ w, __half* __restrict__ out)
{
    int idx = blockIdx.x * blockDim.x + threadIdx.x;   // 512*1024
    if (idx >= 512 * 1024) return;
    int n = idx >> 10, k = idx & 1023;
    __half h = __float2half_rn(w[idx]);
    out[(size_t)n * KCL + k]        = h;
    out[(size_t)n * KCL + 1024 + k] = h;
}

// ----------------------------------------------------------------------------
// Token feature expansion (smem-tiled transpose): bf16 hi/lo
// block = (b, i-tile 256, c-tile 32); grid (16, 2, 32)
// ----------------------------------------------------------------------------
__global__ __launch_bounds__(256)
void feat_tok(const float* __restrict__ ln,
              __nv_bfloat16* __restrict__ Fh,
              __nv_bfloat16* __restrict__ Fl)
{
    __shared__ float s[256 * 33];
    const int t  = threadIdx.x;
    const int c0 = blockIdx.x * 32;
    const int i0 = blockIdx.y * 256;
    const int b  = blockIdx.z;

    #pragma unroll
    for (int it = 0; it < 8; it++) {
        int r  = it * 32 + (t >> 3);
        int cc = (t & 7) * 4;
        float4 v = *(const float4*)(ln + ((size_t)(b * T_ + i0 + r)) * C_ + c0 + cc);
        s[r * 33 + cc]     = v.x;
        s[r * 33 + cc + 1] = v.y;
        s[r * 33 + cc + 2] = v.z;
        s[r * 33 + cc + 3] = v.w;
    }
    __syncthreads();

    const int w = t >> 5, lane = t & 31;
    #pragma unroll
    for (int rep = 0; rep < 4; rep++) {
        const int cl = w * 4 + rep;
        const int n  = b * C_ + c0 + cl;
        #pragma unroll
        for (int it2 = 0; it2 < 8; it2++) {
            int il = it2 * 32 + lane;
            float v = s[il * 33 + cl];
            float s1, c1;
            sincosf(v, &s1, &c1);
            float c2 = 2.f * c1 * c1 - 1.f;
            float s2 = 2.f * s1 * c1;
            float c3 = 2.f * c1 * c2 - c1;
            float s3 = 2.f * c1 * s2 - s1;
            __nv_bfloat16 h[6], l[6];
            split_bf(c1, h[0], l[0]); split_bf(s1, h[1], l[1]);
            split_bf(c2, h[2], l[2]); split_bf(s2, h[3], l[3]);
            split_bf(c3, h[4], l[4]); split_bf(s3, h[5], l[5]);
            size_t base = (size_t)n * KF + (size_t)(i0 + il) * 6;
            __nv_bfloat162* ph = (__nv_bfloat162*)(Fh + base);
            ph[0] = __nv_bfloat162(h[0], h[1]);
            ph[1] = __nv_bfloat162(h[2], h[3]);
            ph[2] = __nv_bfloat162(h[4], h[5]);
            __nv_bfloat162* pl = (__nv_bfloat162*)(Fl + base);
            pl[0] = __nv_bfloat162(l[0], l[1]);
            pl[1] = __nv_bfloat162(l[2], l[3]);
            pl[2] = __nv_bfloat162(l[4], l[5]);
        }
    }
}

// ----------------------------------------------------------------------------
// Channel stage: fused LN2 + feature expansion -> fp16 hi/lo concat layout
// F16 row m (len 6144): [hi(3072) | lo(3072)]. One block per (b,t) row.
// ----------------------------------------------------------------------------
__global__ __launch_bounds__(256)
void feat_ch(const float* __restrict__ x1,
             const float* __restrict__ w,
             const float* __restrict__ b,
             __half* __restrict__ F16)
{
    int row = blockIdx.x;
    const float2* xr = (const float2*)(x1 + (size_t)row * C_);
    float2 v = xr[threadIdx.x];
    float s  = v.x + v.y;
    float sq = v.x * v.x + v.y * v.y;

    __shared__ float ss[8], sqq[8];
    __shared__ float s_mean, s_rstd;
    #pragma unroll
    for (int o = 16; o > 0; o >>= 1) {
        s  += __shfl_down_sync(0xffffffffu, s,  o);
        sq += __shfl_down_sync(0xffffffffu, sq, o);
    }
    int lane = threadIdx.x & 31, wid = threadIdx.x >> 5;
    if (lane == 0) { ss[wid] = s; sqq[wid] = sq; }
    __syncthreads();
    if (wid == 0) {
        float a = (lane < 8) ? ss[lane]  : 0.f;
        float q = (lane < 8) ? sqq[lane] : 0.f;
        #pragma unroll
        for (int o = 4; o > 0; o >>= 1) {
            a += __shfl_down_sync(0xffffffffu, a, o);
            q += __shfl_down_sync(0xffffffffu, q, o);
        }
        if (lane == 0) {
            float m = a * (1.0f / C_);
            float var = q * (1.0f / C_) - m * m;
            s_mean = m;
            s_rstd = rsqrtf(var + 1e-5f);
        }
    }
    __syncthreads();
    float m = s_mean, r = s_rstd;
    float2 wv = ((const float2*)w)[threadIdx.x];
    float2 bv = ((const float2*)b)[threadIdx.x];
    float ln0 = (v.x - m) * r * wv.x + bv.x;
    float ln1 = (v.y - m) * r * wv.y + bv.y;

    #pragma unroll
    for (int q = 0; q < 2; q++) {
        float vv = q ? ln1 : ln0;
        int c = threadIdx.x * 2 + q;
        float s1, c1;
        sincosf(vv, &s1, &c1);
        float c2 = 2.f * c1 * c1 - 1.f;
        float s2 = 2.f * s1 * c1;
        float c3 = 2.f * c1 * c2 - c1;
        float s3 = 2.f * c1 * s2 - s1;
        __half h[6], l[6];
        split_h(c1, h[0], l[0]); split_h(s1, h[1], l[1]);
        split_h(c2, h[2], l[2]); split_h(s2, h[3], l[3]);
        split_h(c3, h[4], l[4]); split_h(s3, h[5], l[5]);
        size_t base = (size_t)row * KCH + (size_t)c * 6;
        __half2* ph = (__half2*)(F16 + base);
        ph[0] = __half2(h[0], h[1]);
        ph[1] = __half2(h[2], h[3]);
        ph[2] = __half2(h[4], h[5]);
        __half2* pl = (__half2*)(F16 + base + KF);
        pl[0] = __half2(l[0], l[1]);
        pl[1] = __half2(l[2], l[3]);
        pl[2] = __half2(l[4], l[5]);
    }
}

// ----------------------------------------------------------------------------
// bf16x3-split TN GEMM (token path): D = Ah*Bh + Ah*Bl + Al*Bh + bias
// MODE 0: write bf16 hi/lo split of D to outH/outL (row stride Ntot)
// MODE 1: token linear: m=(b,c), n=t; outF[(b*T+n)*C+c] = res[..] + D
// ----------------------------------------------------------------------------
template<int MODE>
__global__ __launch_bounds__(256, 1)
void kan_gemm3(const __nv_bfloat16* __restrict__ Ah, const __nv_bfloat16* __restrict__ Al,
               const __nv_bfloat16* __restrict__ Bh, const __nv_bfloat16* __restrict__ Bl,
               const float* __restrict__ bias, const float* __restrict__ res,
               float* __restrict__ outF,
               __nv_bfloat16* __restrict__ outH, __nv_bfloat16* __restrict__ outL,
               int K, int Ntot)
{
    extern __shared__ char smem[];
    const uint32_t sbase = smem_u32(smem);
    const int tid  = threadIdx.x;
    const int wid  = tid >> 5;
    const int lane = tid & 31;
    const int m0 = blockIdx.y * MT;
    const int n0 = blockIdx.x * NT;
    const int wm = wid >> 2;
    const int wn = wid & 3;

    float acc[4][8][4];
    #pragma unroll
    for (int i = 0; i < 4; i++)
        #pragma unroll
        for (int j = 0; j < 8; j++)
            #pragma unroll
            for (int q = 0; q < 4; q++) acc[i][j][q] = 0.f;

    const int NC = K >> 6;

    auto load_chunk = [&](int kc, int buf) {
        const uint32_t sb = sbase + (uint32_t)buf * BUF_STRIDE;
        const size_t kcol = (size_t)kc * BK;
        #pragma unroll
        for (int it = 0; it < 4; it++) {
            int u = tid + it * 256;
            int r = u >> 3, cch = u & 7;
            uint32_t off = r * 128 + ((cch ^ (r & 7)) << 4);
            cpasync16(sb + off, (const char*)(Ah + (size_t)(m0 + r) * K + kcol) + cch * 16);
            cpasync16(sb + OFF_AL + off, (const char*)(Al + (size_t)(m0 + r) * K + kcol) + cch * 16);
        }
        #pragma unroll
        for (int it = 0; it < 8; it++) {
            int u = tid + it * 256;
            int r = u >> 3, cch = u & 7;
            uint32_t off = r * 128 + ((cch ^ (r & 7)) << 4);
            cpasync16(sb + OFF_BH + off, (const char*)(Bh + (size_t)(n0 + r) * K + kcol) + cch * 16);
            cpasync16(sb + OFF_BL + off, (const char*)(Bl + (size_t)(n0 + r) * K + kcol) + cch * 16);
        }
        cp_commit();
    };

    load_chunk(0, 0);

    const int lr = lane & 7;
    const int lq = lane >> 3;

    for (int kc = 0; kc < NC; kc++) {
        if (kc + 1 < NC) { load_chunk(kc + 1, (kc + 1) & 1); cp_wait1(); }
        else             { cp_wait0(); }
        __syncthreads();

        const uint32_t sb = sbase + (uint32_t)(kc & 1) * BUF_STRIDE;
        #pragma unroll
        for (int k16 = 0; k16 < 4; k16++) {
            uint32_t ah[4][4], al[4][4];
            #pragma unroll
            for (int i = 0; i < 4; i++) {
                int row = wm * 64 + i * 16 + lr + (lq & 1) * 8;
                int ch  = (k16 * 2 + (lq >> 1)) ^ (row & 7);
                uint32_t ad = row * 128 + (ch << 4);
                ldsm4(sb + ad, ah[i]);
                ldsm4(sb + OFF_AL + ad, al[i]);
            }
            #pragma unroll
            for (int jp = 0; jp < 4; jp++) {
                int row = wn * 64 + jp * 16 + lr + (lq >> 1) * 8;
                int ch  = (k16 * 2 + (lq & 1)) ^ (row & 7);
                uint32_t ad = row * 128 + (ch << 4);
                uint32_t th[4], tl[4];
                ldsm4(sb + OFF_BH + ad, th);
                ldsm4(sb + OFF_BL + ad, tl);
                #pragma unroll
                for (int i = 0; i < 4; i++) {
                    mma_bf16(acc[i][2*jp],   ah[i], th);
                    mma_bf16(acc[i][2*jp],   ah[i], tl);
                    mma_bf16(acc[i][2*jp],   al[i], th);
                    mma_bf16(acc[i][2*jp+1], ah[i], th + 2);
                    mma_bf16(acc[i][2*jp+1], ah[i], tl + 2);
                    mma_bf16(acc[i][2*jp+1], al[i], th + 2);
                }
            }
        }
        __syncthreads();
    }

    // stage accumulators to smem
    float* stage = (float*)smem;
    {
        const int g = lane >> 2, t2 = (lane & 3) * 2;
        #pragma unroll
        for (int i = 0; i < 4; i++) {
            int row = wm * 64 + i * 16 + g;
            #pragma unroll
            for (int j = 0; j < 8; j++) {
                int col = wn * 64 + j * 8 + t2;
                stage[row * STG_S + col]           = acc[i][j][0];
                stage[row * STG_S + col + 1]       = acc[i][j][1];
                stage[(row + 8) * STG_S + col]     = acc[i][j][2];
                stage[(row + 8) * STG_S + col + 1] = acc[i][j][3];
            }
        }
    }
    __syncthreads();

    if (MODE == 0) {
        for (int u = tid; u < 128 * (NT / 2); u += 256) {
            int r = u >> 7;
            int c = (u & 127) * 2;
            float v0 = stage[r * STG_S + c]     + bias[n0 + c];
            float v1 = stage[r * STG_S + c + 1] + bias[n0 + c + 1];
            __nv_bfloat16 h0, l0, h1, l1;
            split_bf(v0, h0, l0);
            split_bf(v1, h1, l1);
            size_t o = ((size_t)(m0 + r) * Ntot + n0 + c) >> 1;
            ((__nv_bfloat162*)outH)[o] = __nv_bfloat162(h0, h1);
            ((__nv_bfloat162*)outL)[o] = __nv_bfloat162(l0, l1);
        }
    } else {
        const int b  = m0 >> 9;
        const int c0 = m0 & 511;
        for (int nl = wid; nl < NT; nl += 8) {
            int n = n0 + nl;
            float bn = bias[n];
            size_t obase = ((size_t)(b * T_ + n)) * C_ + c0;
            #pragma unroll
            for (int cc = 0; cc < 4; cc++) {
                int c = lane + cc * 32;
                outF[obase + c] = res[obase + c] + stage[c * STG_S + nl] + bn;
            }
        }
    }
}

// ----------------------------------------------------------------------------
// fp16 single-stream TN GEMM (channel path), 4-stage pipeline
// MODE 0: fp16 hi/lo split out: outH[m*Ntot+n] hi, outH[m*Ntot+loOff+n] lo
// MODE 2: outF[m*C_+n0+n] = res[..] + D + bias
// ----------------------------------------------------------------------------
template<int MODE>
__global__ __launch_bounds__(256, 1)
void gemm_std(const __half* __restrict__ A, const __half* __restrict__ Bm,
              const float* __restrict__ bias, const float* __restrict__ res,
              float* __restrict__ outF, __half* __restrict__ outH,
              int K, int Ntot, int loOff)
{
    extern __shared__ char smem[];
    const uint32_t sbase = smem_u32(smem);
    const int tid  = threadIdx.x;
    const int wid  = tid >> 5;
    const int lane = tid & 31;
    const int m0 = blockIdx.y * MT;
    const int n0 = blockIdx.x * NT;
    const int wm = wid >> 2;
    const int wn = wid & 3;

    float acc[4][8][4];
    #pragma unroll
    for (int i = 0; i < 4; i++)
        #pragma unroll
        for (int j = 0; j < 8; j++)
            #pragma unroll
            for (int q = 0; q < 4; q++) acc[i][j][q] = 0.f;

    const int NC = K >> 6;

    auto load_chunk = [&](int kc, int buf) {
        const uint32_t sb = sbase + (uint32_t)buf * SBUF;
        const size_t kcol = (size_t)kc * BK;
        #pragma unroll
        for (int it = 0; it < 4; it++) {
            int u = tid + it * 256;
            int r = u >> 3, cch = u & 7;
            uint32_t off = r * 128 + ((cch ^ (r & 7)) << 4);
            cpasync16(sb + off, (const char*)(A + (size_t)(m0 + r) * K + kcol) + cch * 16);
        }
        #pragma unroll
        for (int it = 0; it < 8; it++) {
            int u = tid + it * 256;
            int r = u >> 3, cch = u & 7;
            uint32_t off = r * 128 + ((cch ^ (r & 7)) << 4);
            cpasync16(sb + SOFF_B + off, (const char*)(Bm + (size_t)(n0 + r) * K + kcol) + cch * 16);
        }
    };

    #pragma unroll
    for (int s = 0; s < 3; s++) {
        if (s < NC) load_chunk(s, s);
        cp_commit();
    }

    const int lr = lane & 7;
    const int lq = lane >> 3;

    for (int kc = 0; kc < NC; kc++) {
        cp_wait2();
        __syncthreads();

        const uint32_t sb = sbase + (uint32_t)(kc & 3) * SBUF;
        #pragma unroll
        for (int k16 = 0; k16 < 4; k16++) {
            uint32_t ah[4][4];
            #pragma unroll
            for (int i = 0; i < 4; i++) {
                int row = wm * 64 + i * 16 + lr + (lq & 1) * 8;
                int ch  = (k16 * 2 + (lq >> 1)) ^ (row & 7);
                ldsm4(sb + row * 128 + (ch << 4), ah[i]);
            }
            #pragma unroll
            for (int jp = 0; jp < 4; jp++) {
                int row = wn * 64 + jp * 16 + lr + (lq >> 1) * 8;
                int ch  = (k16 * 2 + (lq & 1)) ^ (row & 7);
                uint32_t tb[4];
                ldsm4(sb + SOFF_B + row * 128 + (ch << 4), tb);
                #pragma unroll
                for (int i = 0; i < 4; i++) {
                    mma_f16(acc[i][2*jp],   ah[i], tb);
                    mma_f16(acc[i][2*jp+1], ah[i], tb + 2);
                }
            }
        }
        int nk = kc + 3;
        if (nk < NC) load_chunk(nk, nk & 3);
        cp_commit();
    }
    cp_wait0();
    __syncthreads();

    // stage accumulators to smem
    float* stage = (float*)smem;
    {
        const int g = lane >> 2, t2 = (lane & 3) * 2;
        #pragma unroll
        for (int i = 0; i < 4; i++) {
            int row = wm * 64 + i * 16 + g;
            #pragma unroll
            for (int j = 0; j < 8; j++) {
                int col = wn * 64 + j * 8 + t2;
                stage[row * STG_S + col]           = acc[i][j][0];
                stage[row * STG_S + col + 1]       = acc[i][j][1];
                stage[(row + 8) * STG_S + col]     = acc[i][j][2];
                stage[(row + 8) * STG_S + col + 1] = acc[i][j][3];
            }
        }
    }
    __syncthreads();

    if (MODE == 0) {
        for (int u = tid; u < 128 * (NT / 2); u += 256) {
            int r = u >> 7;
            int c = (u & 127) * 2;
            float v0 = stage[r * STG_S + c]     + bias[n0 + c];
            float v1 = stage[r * STG_S + c + 1] + bias[n0 + c + 1];
            __half h0, l0, h1, l1;
            split_h(v0, h0, l0);
            split_h(v1, h1, l1);
            size_t rowb = (size_t)(m0 + r) * Ntot;
            ((__half2*)(outH + rowb + n0 + c))[0]         = __half2(h0, h1);
            ((__half2*)(outH + rowb + loOff + n0 + c))[0] = __half2(l0, l1);
        }
    } else {
        for (int u = tid; u < 128 * (NT / 4); u += 256) {
            int r = u >> 6;
            int c = (u & 63) * 4;
            size_t base = (size_t)(m0 + r) * C_ + n0 + c;
            float4 rv = *(const float4*)(res + base);
            float4 ov;
            ov.x = rv.x + stage[r * STG_S + c]     + bias[n0 + c];
            ov.y = rv.y + stage[r * STG_S + c + 1] + bias[n0 + c + 1];
            ov.z = rv.z + stage[r * STG_S + c + 2] + bias[n0 + c + 2];
            ov.w = rv.w + stage[r * STG_S + c + 3] + bias[n0 + c + 3];
            *(float4*)(outF + base) = ov;
        }
    }
}

// ----------------------------------------------------------------------------
// Launch
// ----------------------------------------------------------------------------
extern "C" void kernel_launch(void* const* d_in, const int* in_sizes, int n_in,
                              void* d_out, int out_size)
{
    const float* x        = (const float*)d_in[0];
    const float* ln1_w    = (const float*)d_in[1];
    const float* ln1_b    = (const float*)d_in[2];
    const float* tok_coef = (const float*)d_in[3];
    const float* tok_kb   = (const float*)d_in[4];
    const float* tok_lw   = (const float*)d_in[5];
    const float* tok_lb   = (const float*)d_in[6];
    const float* ln2_w    = (const float*)d_in[7];
    const float* ln2_b    = (const float*)d_in[8];
    const float* ch_coef  = (const float*)d_in[9];
    const float* ch_kb    = (const float*)d_in[10];
    const float* ch_lw    = (const float*)d_in[11];
    const float* ch_lb    = (const float*)d_in[12];
    float* out = (float*)d_out;

    char* base;
    cudaGetSymbolAddress((void**)&base, g_scratch);
    __nv_bfloat16* pFh  = (__nv_bfloat16*)(base + OFF_FEAT);
    __nv_bfloat16* pFl  = (__nv_bfloat16*)(base + OFF_TOKFL);
    __half*        pF16 = (__half*)       (base + OFF_FEAT);
    __nv_bfloat16* pZh  = (__nv_bfloat16*)(base + OFF_Z);
    __nv_bfloat16* pZl  = (__nv_bfloat16*)(base + OFF_TOKZL);
    __half*        pZ16 = (__half*)       (base + OFF_Z);
    __nv_bfloat16* pTBh = (__nv_bfloat16*)(base + OFF_TBH);
    __nv_bfloat16* pTBl = (__nv_bfloat16*)(base + OFF_TBL);
    __nv_bfloat16* pTWh = (__nv_bfloat16*)(base + OFF_TWH);
    __nv_bfloat16* pTWl = (__nv_bfloat16*)(base + OFF_TWL);
    __half*        pC16 = (__half*)       (base + OFF_C16);
    __half*        pW16 = (__half*)       (base + OFF_W16);
    float*         pLn  = (float*)        (base + OFF_LN);
    float*         pX1  = (float*)        (base + OFF_X1);

    cudaFuncSetAttribute(kan_gemm3<0>, cudaFuncAttributeMaxDynamicSharedMemorySize, SMEM3_SZ);
    cudaFuncSetAttribute(kan_gemm3<1>, cudaFuncAttributeMaxDynamicSharedMemorySize, SMEM3_SZ);
    cudaFuncSetAttribute(gemm_std<0>,  cudaFuncAttributeMaxDynamicSharedMemorySize, SMEMS_SZ);
    cudaFuncSetAttribute(gemm_std<2>,  cudaFuncAttributeMaxDynamicSharedMemorySize, SMEMS_SZ);

    // ---- token mixing (bf16x3, error-critical) ----
    ln_kernel<<<B_ * T_, 256>>>(x, ln1_w, ln1_b, pLn);
    pack_coef3<<<(TD_ * KF + 255) / 256, 256>>>(tok_coef, pTBh, pTBl, TD_);
    pack_w3<<<(T_ * TD_ + 255) / 256, 256>>>(tok_lw, pTWh, pTWl, T_ * TD_);
    feat_tok<<<dim3(C_ / 32, T_ / 256, B_), 256>>>(pLn, pFh, pFl);
    kan_gemm3<0><<<dim3(TD_ / NT, MROWS / MT), 256, SMEM3_SZ>>>(
        pFh, pFl, pTBh, pTBl, tok_kb, nullptr, nullptr, pZh, pZl, KF, TD_);
    kan_gemm3<1><<<dim3(T_ / NT, MROWS / MT), 256, SMEM3_SZ>>>(
        pZh, pZl, pTWh, pTWl, tok_lb, x, pX1, nullptr, nullptr, TD_, T_);

    // ---- channel mixing (fp16 2-term via K-concat) ----
    pack_coef16<<<(1024 * KF + 255) / 256, 256>>>(ch_coef, pC16, 1024);
    pack_w16<<<(512 * 1024 + 255) / 256, 256>>>(ch_lw, pW16);
    feat_ch<<<B_ * T_, 256>>>(pX1, ln2_w, ln2_b, pF16);
    // z2 (M x 1024) = F * coef^T + kbias -> fp16 hi/lo concat (M x 2048)
    gemm_std<0><<<dim3(1024 / NT, MROWS / MT), 256, SMEMS_SZ>>>(
        pF16, pC16, ch_kb, nullptr, nullptr, pZ16, KCH, KCL, 1024);
    // out = x1 + (z2 * lw^T + lb)
    gemm_std<2><<<dim3(C_ / NT, MROWS / MT), 256, SMEMS_SZ>>>(
        pZ16, pW16, ch_lb, pX1, out, nullptr, KCL, 0, 0);
}

// round 6
// speedup vs baseline: 1.0498x; 1.0498x over previous
#include <cuda_runtime.h>
#include <cuda_fp16.h>
#include <math.h>
#include <stdint.h>

#define B_  32
#define T_  512
#define C_  512
#define TD_ 256
#define G_  3
#define MROWS 16384
#define KF  3072               // per-stream feature K
#define KC  6144               // concat K (hi|lo)
#define NTOK 8388608

#define MT 128
#define NT 256
#define BK 64
// fp16 gemm smem: per stage A 16K | B 32K = 48K, 4 stages
#define SOFF_B 16384u
#define SBUF 49152u
#define SMEMS_SZ (4 * 49152)
#define STG_S 261

// ---------------- scratch arena ----------------
#define MB (1024ull * 1024ull)
#define OFF_F     0ull             // features fp16 concat (16384 x 6144) 192MB (both stages)
#define OFF_Z     (192ull * MB)    // z fp16 concat: tok 16MB / ch 64MB
#define OFF_CT    (256ull * MB)    // tok coef dup (256 x 6144) 3MB
#define OFF_WT    (260ull * MB)    // tok lw dup (512 x 512) 0.5MB
#define OFF_CC    (262ull * MB)    // ch coef dup (1024 x 6144) 12MB
#define OFF_WC    (276ull * MB)    // ch lw dup (512 x 2048) 2MB
#define OFF_LN    (278ull * MB)    // LN1 out fp32 32MB
#define OFF_X1    (310ull * MB)    // x1 fp32 32MB
__device__ __align__(256) char g_scratch[342ull * MB];

// ---------------- PTX helpers ----------------
__device__ __forceinline__ uint32_t smem_u32(const void* p) {
    uint32_t a;
    asm("{ .reg .u64 t; cvta.to.shared.u64 t, %1; cvt.u32.u64 %0, t; }" : "=r"(a) : "l"(p));
    return a;
}
__device__ __forceinline__ void cpasync16(uint32_t dst, const void* src) {
    asm volatile("cp.async.cg.shared.global [%0], [%1], 16;" :: "r"(dst), "l"(src));
}
__device__ __forceinline__ void cp_commit() { asm volatile("cp.async.commit_group;" ::: "memory"); }
__device__ __forceinline__ void cp_wait0()  { asm volatile("cp.async.wait_group 0;" ::: "memory"); }
__device__ __forceinline__ void cp_wait2()  { asm volatile("cp.async.wait_group 2;" ::: "memory"); }
__device__ __forceinline__ void ldsm4(uint32_t addr, uint32_t r[4]) {
    asm volatile("ldmatrix.sync.aligned.m8n8.x4.shared.b16 {%0,%1,%2,%3}, [%4];"
                 : "=r"(r[0]), "=r"(r[1]), "=r"(r[2]), "=r"(r[3]) : "r"(addr));
}
__device__ __forceinline__ void mma_f16(float d[4], const uint32_t a[4], const uint32_t b[2]) {
    asm volatile(
        "mma.sync.aligned.m16n8k16.row.col.f32.f16.f16.f32 "
        "{%0,%1,%2,%3}, {%4,%5,%6,%7}, {%8,%9}, {%0,%1,%2,%3};"
        : "+f"(d[0]), "+f"(d[1]), "+f"(d[2]), "+f"(d[3])
        : "r"(a[0]), "r"(a[1]), "r"(a[2]), "r"(a[3]), "r"(b[0]), "r"(b[1]));
}
__device__ __forceinline__ void split_h(float v, __half& h, __half& l) {
    h = __float2half_rn(v);
    l = __float2half_rn(v - __half2float(h));
}
// Polynomial sincos, pure FMA pipe, err < 5e-7 for |v| < 30
__device__ __forceinline__ void fast_sincos(float v, float& s, float& c) {
    float k = rintf(v * 0.3183098861837907f);
    float r = fmaf(-k, 3.14159274101257f, v);
    r = fmaf(-k, -8.742277657347586e-8f, r);
    float r2 = r * r;
    float ps = fmaf(r2, -2.5052108385e-8f, 2.7557319224e-6f);
    ps = fmaf(r2, ps, -1.9841269841e-4f);
    ps = fmaf(r2, ps, 8.3333333333e-3f);
    ps = fmaf(r2, ps, -1.6666666667e-1f);
    ps = fmaf(r2, ps, 1.0f);
    float pc = fmaf(r2, -2.7557319224e-7f, 2.4801587302e-5f);
    pc = fmaf(r2, pc, -1.3888888889e-3f);
    pc = fmaf(r2, pc, 4.1666666667e-2f);
    pc = fmaf(r2, pc, -0.5f);
    float sg = (((int)k) & 1) ? -1.0f : 1.0f;
    s = r * ps * sg;
    c = fmaf(r2, pc, 1.0f) * sg;
}

// ---------------- LayerNorm helper (block over one 512-row) ----------------
__device__ __forceinline__ void ln_row(float2 v, const float* w, const float* b,
                                       float& o0, float& o1) {
    float s  = v.x + v.y;
    float sq = v.x * v.x + v.y * v.y;
    __shared__ float ss[8], sqq[8];
    __shared__ float sm, sr;
    #pragma unroll
    for (int o = 16; o > 0; o >>= 1) {
        s  += __shfl_down_sync(0xffffffffu, s,  o);
        sq += __shfl_down_sync(0xffffffffu, sq, o);
    }
    int lane = threadIdx.x & 31, wid = threadIdx.x >> 5;
    if (lane == 0) { ss[wid] = s; sqq[wid] = sq; }
    __syncthreads();
    if (wid == 0) {
        float a = (lane < 8) ? ss[lane]  : 0.f;
        float q = (lane < 8) ? sqq[lane] : 0.f;
        #pragma unroll
        for (int o = 4; o > 0; o >>= 1) {
            a += __shfl_down_sync(0xffffffffu, a, o);
            q += __shfl_down_sync(0xffffffffu, q, o);
        }
        if (lane == 0) {
            float m = a * (1.0f / 512.f);
            sm = m;
            sr = rsqrtf(q * (1.0f / 512.f) - m * m + 1e-5f);
        }
    }
    __syncthreads();
    float2 wv = ((const float2*)w)[threadIdx.x];
    float2 bv = ((const float2*)b)[threadIdx.x];
    o0 = (v.x - sm) * sr * wv.x + bv.x;
    o1 = (v.y - sm) * sr * wv.y + bv.y;
}

__global__ void ln_kernel(const float* __restrict__ x, const float* __restrict__ w,
                          const float* __restrict__ b, float* __restrict__ out)
{
    int row = blockIdx.x;
    float2 v = ((const float2*)(x + (size_t)row * C_))[threadIdx.x];
    float o0, o1;
    ln_row(v, w, b, o0, o1);
    ((float2*)(out + (size_t)row * C_))[threadIdx.x] = make_float2(o0, o1);
}

// ---------------- packs: coef (2,O,512,3)->fp16 dup (O x 6144), lw->fp16 dup ----
// coef k-order within 3072: i*6 + g*2 + trig
__global__ void pack_stage(const float* __restrict__ coef, const float* __restrict__ lw,
                           __half* __restrict__ Cd, __half* __restrict__ Wd,
                           int O, int LWN, int LWK)
{
    int idx = blockIdx.x * blockDim.x + threadIdx.x;
    int nc = O * KF;
    if (idx < nc) {
        int o = idx / KF, r = idx % KF;
        int i = r / 6, rr = r % 6, g = rr >> 1, trig = rr & 1;
        __half h = __float2half_rn(coef[(((size_t)trig * O + o) * 512 + i) * G_ + g]);
        Cd[(size_t)o * KC + r]      = h;
        Cd[(size_t)o * KC + KF + r] = h;
    } else {
        int j = idx - nc;
        if (j < LWN * LWK) {
            int n = j / LWK, k = j % LWK;
            __half h = __float2half_rn(lw[j]);
            Wd[(size_t)n * (2 * LWK) + k]       = h;
            Wd[(size_t)n * (2 * LWK) + LWK + k] = h;
        }
    }
}

// ---------------- token features (transposed read): fp16 concat rows ----------
__global__ __launch_bounds__(256)
void feat_tok(const float* __restrict__ ln, __half* __restrict__ F)
{
    __shared__ float s[256 * 33];
    const int t = threadIdx.x;
    const int c0 = blockIdx.x * 32, i0 = blockIdx.y * 256, b = blockIdx.z;
    #pragma unroll
    for (int it = 0; it < 8; it++) {
        int r = it * 32 + (t >> 3), cc = (t & 7) * 4;
        float4 v = *(const float4*)(ln + ((size_t)(b * T_ + i0 + r)) * C_ + c0 + cc);
        s[r * 33 + cc] = v.x; s[r * 33 + cc + 1] = v.y;
        s[r * 33 + cc + 2] = v.z; s[r * 33 + cc + 3] = v.w;
    }
    __syncthreads();
    const int w = t >> 5, lane = t & 31;
    #pragma unroll
    for (int rep = 0; rep < 4; rep++) {
        const int cl = w * 4 + rep;
        const size_t n = (size_t)(b * C_ + c0 + cl);
        #pragma unroll
        for (int it2 = 0; it2 < 8; it2++) {
            int il = it2 * 32 + lane;
            float v = s[il * 33 + cl];
            float s1, c1;
            fast_sincos(v, s1, c1);
            float c2 = fmaf(2.f * c1, c1, -1.f);
            float s2 = 2.f * s1 * c1;
            float c3 = fmaf(2.f * c1, c2, -c1);
            float s3 = fmaf(2.f * c1, s2, -s1);
            __half h[6], l[6];
            split_h(c1, h[0], l[0]); split_h(s1, h[1], l[1]);
            split_h(c2, h[2], l[2]); split_h(s2, h[3], l[3]);
            split_h(c3, h[4], l[4]); split_h(s3, h[5], l[5]);
            size_t base = n * KC + (size_t)(i0 + il) * 6;
            __half2* ph = (__half2*)(F + base);
            ph[0] = __half2(h[0], h[1]); ph[1] = __half2(h[2], h[3]); ph[2] = __half2(h[4], h[5]);
            __half2* pl = (__half2*)(F + base + KF);
            pl[0] = __half2(l[0], l[1]); pl[1] = __half2(l[2], l[3]); pl[2] = __half2(l[4], l[5]);
        }
    }
}

// ---------------- channel features: fused LN2 + expansion -----------------
__global__ __launch_bounds__(256)
void feat_ch(const float* __restrict__ x1, const float* __restrict__ w,
             const float* __restrict__ b, __half* __restrict__ F)
{
    int row = blockIdx.x;
    float2 v = ((const float2*)(x1 + (size_t)row * C_))[threadIdx.x];
    float ln0, ln1;
    ln_row(v, w, b, ln0, ln1);
    #pragma unroll
    for (int q = 0; q < 2; q++) {
        float vv = q ? ln1 : ln0;
        int c = threadIdx.x * 2 + q;
        float s1, c1;
        fast_sincos(vv, s1, c1);
        float c2 = fmaf(2.f * c1, c1, -1.f);
        float s2 = 2.f * s1 * c1;
        float c3 = fmaf(2.f * c1, c2, -c1);
        float s3 = fmaf(2.f * c1, s2, -s1);
        __half h[6], l[6];
        split_h(c1, h[0], l[0]); split_h(s1, h[1], l[1]);
        split_h(c2, h[2], l[2]); split_h(s2, h[3], l[3]);
        split_h(c3, h[4], l[4]); split_h(s3, h[5], l[5]);
        size_t base = (size_t)row * KC + (size_t)c * 6;
        __half2* ph = (__half2*)(F + base);
        ph[0] = __half2(h[0], h[1]); ph[1] = __half2(h[2], h[3]); ph[2] = __half2(h[4], h[5]);
        __half2* pl = (__half2*)(F + base + KF);
        pl[0] = __half2(l[0], l[1]); pl[1] = __half2(l[2], l[3]); pl[2] = __half2(l[4], l[5]);
    }
}

// ---------------- fp16 TN GEMM, 4-stage cp.async, CTA 128x256 ----------------
// MODE 0: fp16 hi/lo split out: outH[m*Ntot + n] / outH[m*Ntot + loOff + n]
// MODE 1: m=(b,c), n=t: outF[(b*T+n)*C+c] = res[..] + D + bias
// MODE 2: outF[m*C+n] = res[..] + D + bias
template<int MODE>
__global__ __launch_bounds__(256, 1)
void gemm_std(const __half* __restrict__ A, const __half* __restrict__ Bm,
              const float* __restrict__ bias, const float* __restrict__ res,
              float* __restrict__ outF, __half* __restrict__ outH,
              int K, int Ntot, int loOff)
{
    extern __shared__ char smem[];
    const uint32_t sbase = smem_u32(smem);
    const int tid = threadIdx.x, wid = tid >> 5, lane = tid & 31;
    const int m0 = blockIdx.y * MT, n0 = blockIdx.x * NT;
    const int wm = wid >> 2, wn = wid & 3;

    float acc[4][8][4];
    #pragma unroll
    for (int i = 0; i < 4; i++)
        #pragma unroll
        for (int j = 0; j < 8; j++)
            #pragma unroll
            for (int q = 0; q < 4; q++) acc[i][j][q] = 0.f;

    const int NC = K >> 6;

    auto load_chunk = [&](int kc, int buf) {
        const uint32_t sb = sbase + (uint32_t)buf * SBUF;
        const size_t kcol = (size_t)kc * BK;
        #pragma unroll
        for (int it = 0; it < 4; it++) {
            int u = tid + it * 256;
            int r = u >> 3, cch = u & 7;
            uint32_t off = r * 128 + ((cch ^ (r & 7)) << 4);
            cpasync16(sb + off, (const char*)(A + (size_t)(m0 + r) * K + kcol) + cch * 16);
        }
        #pragma unroll
        for (int it = 0; it < 8; it++) {
            int u = tid + it * 256;
            int r = u >> 3, cch = u & 7;
            uint32_t off = r * 128 + ((cch ^ (r & 7)) << 4);
            cpasync16(sb + SOFF_B + off, (const char*)(Bm + (size_t)(n0 + r) * K + kcol) + cch * 16);
        }
    };

    #pragma unroll
    for (int s = 0; s < 3; s++) {
        if (s < NC) load_chunk(s, s);
        cp_commit();
    }

    const int lr = lane & 7, lq = lane >> 3;

    for (int kc = 0; kc < NC; kc++) {
        cp_wait2();
        __syncthreads();
        const uint32_t sb = sbase + (uint32_t)(kc & 3) * SBUF;
        #pragma unroll
        for (int k16 = 0; k16 < 4; k16++) {
            uint32_t ah[4][4];
            #pragma unroll
            for (int i = 0; i < 4; i++) {
                int row = wm * 64 + i * 16 + lr + (lq & 1) * 8;
                int ch  = (k16 * 2 + (lq >> 1)) ^ (row & 7);
                ldsm4(sb + row * 128 + (ch << 4), ah[i]);
            }
            #pragma unroll
            for (int jp = 0; jp < 4; jp++) {
                int row = wn * 64 + jp * 16 + lr + (lq >> 1) * 8;
                int ch  = (k16 * 2 + (lq & 1)) ^ (row & 7);
                uint32_t tb[4];
                ldsm4(sb + SOFF_B + row * 128 + (ch << 4), tb);
                #pragma unroll
                for (int i = 0; i < 4; i++) {
                    mma_f16(acc[i][2*jp],   ah[i], tb);
                    mma_f16(acc[i][2*jp+1], ah[i], tb + 2);
                }
            }
        }
        int nk = kc + 3;
        if (nk < NC) load_chunk(nk, nk & 3);
        cp_commit();
    }
    cp_wait0();
    __syncthreads();

    // stage accumulators to smem
    float* stage = (float*)smem;
    {
        const int g = lane >> 2, t2 = (lane & 3) * 2;
        #pragma unroll
        for (int i = 0; i < 4; i++) {
            int row = wm * 64 + i * 16 + g;
            #pragma unroll
            for (int j = 0; j < 8; j++) {
                int col = wn * 64 + j * 8 + t2;
                stage[row * STG_S + col]           = acc[i][j][0];
                stage[row * STG_S + col + 1]       = acc[i][j][1];
                stage[(row + 8) * STG_S + col]     = acc[i][j][2];
                stage[(row + 8) * STG_S + col + 1] = acc[i][j][3];
            }
        }
    }
    __syncthreads();

    if (MODE == 0) {
        for (int u = tid; u < 128 * (NT / 2); u += 256) {
            int r = u >> 7;
            int c = (u & 127) * 2;
            float v0 = stage[r * STG_S + c]     + bias[n0 + c];
            float v1 = stage[r * STG_S + c + 1] + bias[n0 + c + 1];
            __half h0, l0, h1, l1;
            split_h(v0, h0, l0);
            split_h(v1, h1, l1);
            size_t rowb = (size_t)(m0 + r) * Ntot;
            ((__half2*)(outH + rowb + n0 + c))[0]         = __half2(h0, h1);
            ((__half2*)(outH + rowb + loOff + n0 + c))[0] = __half2(l0, l1);
        }
    } else if (MODE == 1) {
        const int b = m0 >> 9, c0 = m0 & 511;
        for (int nl = wid; nl < NT; nl += 8) {
            int n = n0 + nl;
            float bn = bias[n];
            size_t obase = ((size_t)(b * T_ + n)) * C_ + c0;
            #pragma unroll
            for (int cc = 0; cc < 4; cc++) {
                int c = lane + cc * 32;
                outF[obase + c] = res[obase + c] + stage[c * STG_S + nl] + bn;
            }
        }
    } else {
        for (int u = tid; u < 128 * (NT / 4); u += 256) {
            int r = u >> 6;
            int c = (u & 63) * 4;
            size_t base = (size_t)(m0 + r) * C_ + n0 + c;
            float4 rv = *(const float4*)(res + base);
            float4 ov;
            ov.x = rv.x + stage[r * STG_S + c]     + bias[n0 + c];
            ov.y = rv.y + stage[r * STG_S + c + 1] + bias[n0 + c + 1];
            ov.z = rv.z + stage[r * STG_S + c + 2] + bias[n0 + c + 2];
            ov.w = rv.w + stage[r * STG_S + c + 3] + bias[n0 + c + 3];
            *(float4*)(outF + base) = ov;
        }
    }
}

// ---------------- launch ----------------
extern "C" void kernel_launch(void* const* d_in, const int* in_sizes, int n_in,
                              void* d_out, int out_size)
{
    const float* x        = (const float*)d_in[0];
    const float* ln1_w    = (const float*)d_in[1];
    const float* ln1_b    = (const float*)d_in[2];
    const float* tok_coef = (const float*)d_in[3];
    const float* tok_kb   = (const float*)d_in[4];
    const float* tok_lw   = (const float*)d_in[5];
    const float* tok_lb   = (const float*)d_in[6];
    const float* ln2_w    = (const float*)d_in[7];
    const float* ln2_b    = (const float*)d_in[8];
    const float* ch_coef  = (const float*)d_in[9];
    const float* ch_kb    = (const float*)d_in[10];
    const float* ch_lw    = (const float*)d_in[11];
    const float* ch_lb    = (const float*)d_in[12];
    float* out = (float*)d_out;

    char* base;
    cudaGetSymbolAddress((void**)&base, g_scratch);
    __half* pF  = (__half*)(base + OFF_F);
    __half* pZ  = (__half*)(base + OFF_Z);
    __half* pCT = (__half*)(base + OFF_CT);
    __half* pWT = (__half*)(base + OFF_WT);
    __half* pCC = (__half*)(base + OFF_CC);
    __half* pWC = (__half*)(base + OFF_WC);
    float*  pLn = (float*)(base + OFF_LN);
    float*  pX1 = (float*)(base + OFF_X1);

    cudaFuncSetAttribute(gemm_std<0>, cudaFuncAttributeMaxDynamicSharedMemorySize, SMEMS_SZ);
    cudaFuncSetAttribute(gemm_std<1>, cudaFuncAttributeMaxDynamicSharedMemorySize, SMEMS_SZ);
    cudaFuncSetAttribute(gemm_std<2>, cudaFuncAttributeMaxDynamicSharedMemorySize, SMEMS_SZ);

    // ---- token mixing ----
    ln_kernel<<<B_ * T_, 256>>>(x, ln1_w, ln1_b, pLn);
    pack_stage<<<(TD_ * KF + T_ * TD_ + 255) / 256, 256>>>(
        tok_coef, tok_lw, pCT, pWT, TD_, T_, TD_);
    feat_tok<<<dim3(C_ / 32, T_ / 256, B_), 256>>>(pLn, pF);
    // z (M x 256) = F * coef^T + kbias -> fp16 hi/lo concat (row len 512)
    gemm_std<0><<<dim3(1, MROWS / MT), 256, SMEMS_SZ>>>(
        pF, pCT, tok_kb, nullptr, nullptr, pZ, KC, 512, 256);
    // x1 = x + transpose(z * lw^T + lb)
    gemm_std<1><<<dim3(T_ / NT, MROWS / MT), 256, SMEMS_SZ>>>(
        pZ, pWT, tok_lb, x, pX1, nullptr, 512, 0, 0);

    // ---- channel mixing ----
    pack_stage<<<(1024 * KF + 512 * 1024 + 255) / 256, 256>>>(
        ch_coef, ch_lw, pCC, pWC, 1024, 512, 1024);
    feat_ch<<<B_ * T_, 256>>>(pX1, ln2_w, ln2_b, pF);
    // z2 (M x 1024) -> fp16 hi/lo concat (row len 2048)
    gemm_std<0><<<dim3(1024 / NT, MROWS / MT), 256, SMEMS_SZ>>>(
        pF, pCC, ch_kb, nullptr, nullptr, pZ, KC, 2048, 1024);
    // out = x1 + (z2 * lw^T + lb)
    gemm_std<2><<<dim3(C_ / NT, MROWS / MT), 256, SMEMS_SZ>>>(
        pZ, pWC, ch_lb, pX1, out, nullptr, 2048, 0, 0);
}

// round 8
// speedup vs baseline: 1.9203x; 1.8292x over previous
#include <cuda_runtime.h>
#include <cuda_fp16.h>
#include <math.h>
#include <stdint.h>

#define B_  32
#define T_  512
#define C_  512
#define TD_ 256
#define G_  3
#define MROWS 16384
#define KF  3072               // feature K (single stream)
#define NTOK 8388608

#define MT 128
#define NT 256
#define BK 64
// fp16 gemm smem: per stage A 16K | B 32K = 48K, 4 stages
#define SOFF_B 16384u
#define SBUF 49152u
#define SMEMS_SZ (4 * 49152)
#define STG_S 261

// ---------------- scratch arena ----------------
#define MB (1024ull * 1024ull)
#define OFF_F     0ull             // features fp16 (16384 x 3072) 96MB (both stages)
#define OFF_Z     (96ull  * MB)    // z fp16: tok 8MB / ch 32MB
#define OFF_CT    (160ull * MB)    // tok coef (256 x 3072) 1.5MB
#define OFF_WT    (162ull * MB)    // tok lw fp16 (512 x 256) 0.25MB
#define OFF_CC    (164ull * MB)    // ch coef (1024 x 3072) 6MB
#define OFF_WC    (172ull * MB)    // ch lw fp16 (512 x 1024) 1MB
#define OFF_LN    (174ull * MB)    // LN1 out fp32 32MB
#define OFF_X1    (206ull * MB)    // x1 fp32 32MB
__device__ __align__(256) char g_scratch[240ull * MB];

// ---------------- PTX helpers ----------------
__device__ __forceinline__ uint32_t smem_u32(const void* p) {
    uint32_t a;
    asm("{ .reg .u64 t; cvta.to.shared.u64 t, %1; cvt.u32.u64 %0, t; }" : "=r"(a) : "l"(p));
    return a;
}
__device__ __forceinline__ void cpasync16(uint32_t dst, const void* src) {
    asm volatile("cp.async.cg.shared.global [%0], [%1], 16;" :: "r"(dst), "l"(src));
}
__device__ __forceinline__ void cp_commit() { asm volatile("cp.async.commit_group;" ::: "memory"); }
__device__ __forceinline__ void cp_wait0()  { asm volatile("cp.async.wait_group 0;" ::: "memory"); }
__device__ __forceinline__ void cp_wait2()  { asm volatile("cp.async.wait_group 2;" ::: "memory"); }
__device__ __forceinline__ void ldsm4(uint32_t addr, uint32_t r[4]) {
    asm volatile("ldmatrix.sync.aligned.m8n8.x4.shared.b16 {%0,%1,%2,%3}, [%4];"
                 : "=r"(r[0]), "=r"(r[1]), "=r"(r[2]), "=r"(r[3]) : "r"(addr));
}
__device__ __forceinline__ void mma_f16(float d[4], const uint32_t a[4], const uint32_t b[2]) {
    asm volatile(
        "mma.sync.aligned.m16n8k16.row.col.f32.f16.f16.f32 "
        "{%0,%1,%2,%3}, {%4,%5,%6,%7}, {%8,%9}, {%0,%1,%2,%3};"
        : "+f"(d[0]), "+f"(d[1]), "+f"(d[2]), "+f"(d[3])
        : "r"(a[0]), "r"(a[1]), "r"(a[2]), "r"(a[3]), "r"(b[0]), "r"(b[1]));
}
// Polynomial sincos, pure FMA pipe, err < 5e-7 for |v| < 30
__device__ __forceinline__ void fast_sincos(float v, float& s, float& c) {
    float k = rintf(v * 0.3183098861837907f);
    float r = fmaf(-k, 3.14159274101257f, v);
    r = fmaf(-k, -8.742277657347586e-8f, r);
    float r2 = r * r;
    float ps = fmaf(r2, -2.5052108385e-8f, 2.7557319224e-6f);
    ps = fmaf(r2, ps, -1.9841269841e-4f);
    ps = fmaf(r2, ps, 8.3333333333e-3f);
    ps = fmaf(r2, ps, -1.6666666667e-1f);
    ps = fmaf(r2, ps, 1.0f);
    float pc = fmaf(r2, -2.7557319224e-7f, 2.4801587302e-5f);
    pc = fmaf(r2, pc, -1.3888888889e-3f);
    pc = fmaf(r2, pc, 4.1666666667e-2f);
    pc = fmaf(r2, pc, -0.5f);
    float sg = (((int)k) & 1) ? -1.0f : 1.0f;
    s = r * ps * sg;
    c = fmaf(r2, pc, 1.0f) * sg;
}

// ---------------- LayerNorm helper (block over one 512-row) ----------------
__device__ __forceinline__ void ln_row(float2 v, const float* w, const float* b,
                                       float& o0, float& o1) {
    float s  = v.x + v.y;
    float sq = v.x * v.x + v.y * v.y;
    __shared__ float ss[8], sqq[8];
    __shared__ float sm, sr;
    #pragma unroll
    for (int o = 16; o > 0; o >>= 1) {
        s  += __shfl_down_sync(0xffffffffu, s,  o);
        sq += __shfl_down_sync(0xffffffffu, sq, o);
    }
    int lane = threadIdx.x & 31, wid = threadIdx.x >> 5;
    if (lane == 0) { ss[wid] = s; sqq[wid] = sq; }
    __syncthreads();
    if (wid == 0) {
        float a = (lane < 8) ? ss[lane]  : 0.f;
        float q = (lane < 8) ? sqq[lane] : 0.f;
        #pragma unroll
        for (int o = 4; o > 0; o >>= 1) {
            a += __shfl_down_sync(0xffffffffu, a, o);
            q += __shfl_down_sync(0xffffffffu, q, o);
        }
        if (lane == 0) {
            float m = a * (1.0f / 512.f);
            sm = m;
            sr = rsqrtf(q * (1.0f / 512.f) - m * m + 1e-5f);
        }
    }
    __syncthreads();
    float2 wv = ((const float2*)w)[threadIdx.x];
    float2 bv = ((const float2*)b)[threadIdx.x];
    o0 = (v.x - sm) * sr * wv.x + bv.x;
    o1 = (v.y - sm) * sr * wv.y + bv.y;
}

__global__ void ln_kernel(const float* __restrict__ x, const float* __restrict__ w,
                          const float* __restrict__ b, float* __restrict__ out)
{
    int row = blockIdx.x;
    float2 v = ((const float2*)(x + (size_t)row * C_))[threadIdx.x];
    float o0, o1;
    ln_row(v, w, b, o0, o1);
    ((float2*)(out + (size_t)row * C_))[threadIdx.x] = make_float2(o0, o1);
}

// ---- packs: coef (2,O,512,3)->fp16 (O x 3072, k=i*6+g*2+trig); lw -> fp16 as-is
__global__ void pack_stage(const float* __restrict__ coef, const float* __restrict__ lw,
                           __half* __restrict__ Cd, __half* __restrict__ Wd,
                           int O, int LWTOT)
{
    int idx = blockIdx.x * blockDim.x + threadIdx.x;
    int nc = O * KF;
    if (idx < nc) {
        int o = idx / KF, r = idx % KF;
        int i = r / 6, rr = r % 6, g = rr >> 1, trig = rr & 1;
        Cd[idx] = __float2half_rn(coef[(((size_t)trig * O + o) * 512 + i) * G_ + g]);
    } else {
        int j = idx - nc;
        if (j < LWTOT) Wd[j] = __float2half_rn(lw[j]);
    }
}

// ---------------- token features (transposed read): fp16 rows ----------------
__global__ __launch_bounds__(256)
void feat_tok(const float* __restrict__ ln, __half* __restrict__ F)
{
    __shared__ float s[256 * 33];
    const int t = threadIdx.x;
    const int c0 = blockIdx.x * 32, i0 = blockIdx.y * 256, b = blockIdx.z;
    #pragma unroll
    for (int it = 0; it < 8; it++) {
        int r = it * 32 + (t >> 3), cc = (t & 7) * 4;
        float4 v = *(const float4*)(ln + ((size_t)(b * T_ + i0 + r)) * C_ + c0 + cc);
        s[r * 33 + cc] = v.x; s[r * 33 + cc + 1] = v.y;
        s[r * 33 + cc + 2] = v.z; s[r * 33 + cc + 3] = v.w;
    }
    __syncthreads();
    const int w = t >> 5, lane = t & 31;
    #pragma unroll
    for (int rep = 0; rep < 4; rep++) {
        const int cl = w * 4 + rep;
        const size_t n = (size_t)(b * C_ + c0 + cl);
        #pragma unroll
        for (int it2 = 0; it2 < 8; it2++) {
            int il = it2 * 32 + lane;
            float v = s[il * 33 + cl];
            float s1, c1;
            fast_sincos(v, s1, c1);
            float c2 = fmaf(2.f * c1, c1, -1.f);
            float s2 = 2.f * s1 * c1;
            float c3 = fmaf(2.f * c1, c2, -c1);
            float s3 = fmaf(2.f * c1, s2, -s1);
            size_t base = n * KF + (size_t)(i0 + il) * 6;
            __half2* p = (__half2*)(F + base);
            p[0] = __floats2half2_rn(c1, s1);
            p[1] = __floats2half2_rn(c2, s2);
            p[2] = __floats2half2_rn(c3, s3);
        }
    }
}

// ---------------- channel features: fused LN2 + expansion -----------------
__global__ __launch_bounds__(256)
void feat_ch(const float* __restrict__ x1, const float* __restrict__ w,
             const float* __restrict__ b, __half* __restrict__ F)
{
    int row = blockIdx.x;
    float2 v = ((const float2*)(x1 + (size_t)row * C_))[threadIdx.x];
    float ln0, ln1;
    ln_row(v, w, b, ln0, ln1);
    #pragma unroll
    for (int q = 0; q < 2; q++) {
        float vv = q ? ln1 : ln0;
        int c = threadIdx.x * 2 + q;
        float s1, c1;
        fast_sincos(vv, s1, c1);
        float c2 = fmaf(2.f * c1, c1, -1.f);
        float s2 = 2.f * s1 * c1;
        float c3 = fmaf(2.f * c1, c2, -c1);
        float s3 = fmaf(2.f * c1, s2, -s1);
        size_t base = (size_t)row * KF + (size_t)c * 6;
        __half2* p = (__half2*)(F + base);
        p[0] = __floats2half2_rn(c1, s1);
        p[1] = __floats2half2_rn(c2, s2);
        p[2] = __floats2half2_rn(c3, s3);
    }
}

// ---------------- fp16 TN GEMM, 4-stage cp.async, CTA 128x256 ----------------
// MODE 0: fp16 out: outH[m*Ntot + n] = D + bias
// MODE 1: m=(b,c), n=t: outF[(b*T+n)*C+c] = res[..] + D + bias
// MODE 2: outF[m*C+n] = res[..] + D + bias
template<int MODE>
__global__ __launch_bounds__(256, 1)
void gemm_std(const __half* __restrict__ A, const __half* __restrict__ Bm,
              const float* __restrict__ bias, const float* __restrict__ res,
              float* __restrict__ outF, __half* __restrict__ outH,
              int K, int Ntot)
{
    extern __shared__ char smem[];
    const uint32_t sbase = smem_u32(smem);
    const int tid = threadIdx.x, wid = tid >> 5, lane = tid & 31;
    const int m0 = blockIdx.y * MT, n0 = blockIdx.x * NT;
    const int wm = wid >> 2, wn = wid & 3;

    float acc[4][8][4];
    #pragma unroll
    for (int i = 0; i < 4; i++)
        #pragma unroll
        for (int j = 0; j < 8; j++)
            #pragma unroll
            for (int q = 0; q < 4; q++) acc[i][j][q] = 0.f;

    const int NC = K >> 6;

    auto load_chunk = [&](int kc, int buf) {
        const uint32_t sb = sbase + (uint32_t)buf * SBUF;
        const size_t kcol = (size_t)kc * BK;
        #pragma unroll
        for (int it = 0; it < 4; it++) {
            int u = tid + it * 256;
            int r = u >> 3, cch = u & 7;
            uint32_t off = r * 128 + ((cch ^ (r & 7)) << 4);
            cpasync16(sb + off, (const char*)(A + (size_t)(m0 + r) * K + kcol) + cch * 16);
        }
        #pragma unroll
        for (int it = 0; it < 8; it++) {
            int u = tid + it * 256;
            int r = u >> 3, cch = u & 7;
            uint32_t off = r * 128 + ((cch ^ (r & 7)) << 4);
            cpasync16(sb + SOFF_B + off, (const char*)(Bm + (size_t)(n0 + r) * K + kcol) + cch * 16);
        }
    };

    #pragma unroll
    for (int s = 0; s < 3; s++) {
        if (s < NC) load_chunk(s, s);
        cp_commit();
    }

    const int lr = lane & 7, lq = lane >> 3;

    for (int kc = 0; kc < NC; kc++) {
        cp_wait2();
        __syncthreads();
        const uint32_t sb = sbase + (uint32_t)(kc & 3) * SBUF;
        #pragma unroll
        for (int k16 = 0; k16 < 4; k16++) {
            uint32_t ah[4][4];
            #pragma unroll
            for (int i = 0; i < 4; i++) {
                int row = wm * 64 + i * 16 + lr + (lq & 1) * 8;
                int ch  = (k16 * 2 + (lq >> 1)) ^ (row & 7);
                ldsm4(sb + row * 128 + (ch << 4), ah[i]);
            }
            #pragma unroll
            for (int jp = 0; jp < 4; jp++) {
                int row = wn * 64 + jp * 16 + lr + (lq >> 1) * 8;
                int ch  = (k16 * 2 + (lq & 1)) ^ (row & 7);
                uint32_t tb[4];
                ldsm4(sb + SOFF_B + row * 128 + (ch << 4), tb);
                #pragma unroll
                for (int i = 0; i < 4; i++) {
                    mma_f16(acc[i][2*jp],   ah[i], tb);
                    mma_f16(acc[i][2*jp+1], ah[i], tb + 2);
                }
            }
        }
        int nk = kc + 3;
        if (nk < NC) load_chunk(nk, nk & 3);
        cp_commit();
    }
    cp_wait0();
    __syncthreads();

    // stage accumulators to smem
    float* stage = (float*)smem;
    {
        const int g = lane >> 2, t2 = (lane & 3) * 2;
        #pragma unroll
        for (int i = 0; i < 4; i++) {
            int row = wm * 64 + i * 16 + g;
            #pragma unroll
            for (int j = 0; j < 8; j++) {
                int col = wn * 64 + j * 8 + t2;
                stage[row * STG_S + col]           = acc[i][j][0];
                stage[row * STG_S + col + 1]       = acc[i][j][1];
                stage[(row + 8) * STG_S + col]     = acc[i][j][2];
                stage[(row + 8) * STG_S + col + 1] = acc[i][j][3];
            }
        }
    }
    __syncthreads();

    if (MODE == 0) {
        for (int u = tid; u < 128 * (NT / 2); u += 256) {
            int r = u >> 7;
            int c = (u & 127) * 2;
            float v0 = stage[r * STG_S + c]     + bias[n0 + c];
            float v1 = stage[r * STG_S + c + 1] + bias[n0 + c + 1];
            size_t rowb = (size_t)(m0 + r) * Ntot;
            ((__half2*)(outH + rowb + n0 + c))[0] = __floats2half2_rn(v0, v1);
        }
    } else if (MODE == 1) {
        const int b = m0 >> 9, c0 = m0 & 511;
        for (int nl = wid; nl < NT; nl += 8) {
            int n = n0 + nl;
            float bn = bias[n];
            size_t obase = ((size_t)(b * T_ + n)) * C_ + c0;
            #pragma unroll
            for (int cc = 0; cc < 4; cc++) {
                int c = lane + cc * 32;
                outF[obase + c] = res[obase + c] + stage[c * STG_S + nl] + bn;
            }
        }
    } else {
        for (int u = tid; u < 128 * (NT / 4); u += 256) {
            int r = u >> 6;
            int c = (u & 63) * 4;
            size_t base = (size_t)(m0 + r) * C_ + n0 + c;
            float4 rv = *(const float4*)(res + base);
            float4 ov;
            ov.x = rv.x + stage[r * STG_S + c]     + bias[n0 + c];
            ov.y = rv.y + stage[r * STG_S + c + 1] + bias[n0 + c + 1];
            ov.z = rv.z + stage[r * STG_S + c + 2] + bias[n0 + c + 2];
            ov.w = rv.w + stage[r * STG_S + c + 3] + bias[n0 + c + 3];
            *(float4*)(outF + base) = ov;
        }
    }
}

// ---------------- launch ----------------
extern "C" void kernel_launch(void* const* d_in, const int* in_sizes, int n_in,
                              void* d_out, int out_size)
{
    const float* x        = (const float*)d_in[0];
    const float* ln1_w    = (const float*)d_in[1];
    const float* ln1_b    = (const float*)d_in[2];
    const float* tok_coef = (const float*)d_in[3];
    const float* tok_kb   = (const float*)d_in[4];
    const float* tok_lw   = (const float*)d_in[5];
    const float* tok_lb   = (const float*)d_in[6];
    const float* ln2_w    = (const float*)d_in[7];
    const float* ln2_b    = (const float*)d_in[8];
    const float* ch_coef  = (const float*)d_in[9];
    const float* ch_kb    = (const float*)d_in[10];
    const float* ch_lw    = (const float*)d_in[11];
    const float* ch_lb    = (const float*)d_in[12];
    float* out = (float*)d_out;

    char* base;
    cudaGetSymbolAddress((void**)&base, g_scratch);
    __half* pF  = (__half*)(base + OFF_F);
    __half* pZ  = (__half*)(base + OFF_Z);
    __half* pCT = (__half*)(base + OFF_CT);
    __half* pWT = (__half*)(base + OFF_WT);
    __half* pCC = (__half*)(base + OFF_CC);
    __half* pWC = (__half*)(base + OFF_WC);
    float*  pLn = (float*)(base + OFF_LN);
    float*  pX1 = (float*)(base + OFF_X1);

    cudaFuncSetAttribute(gemm_std<0>, cudaFuncAttributeMaxDynamicSharedMemorySize, SMEMS_SZ);
    cudaFuncSetAttribute(gemm_std<1>, cudaFuncAttributeMaxDynamicSharedMemorySize, SMEMS_SZ);
    cudaFuncSetAttribute(gemm_std<2>, cudaFuncAttributeMaxDynamicSharedMemorySize, SMEMS_SZ);

    // ---- token mixing ----
    ln_kernel<<<B_ * T_, 256>>>(x, ln1_w, ln1_b, pLn);
    pack_stage<<<(TD_ * KF + T_ * TD_ + 255) / 256, 256>>>(
        tok_coef, tok_lw, pCT, pWT, TD_, T_ * TD_);
    feat_tok<<<dim3(C_ / 32, T_ / 256, B_), 256>>>(pLn, pF);
    // z (M x 256) = F * coef^T + kbias  (fp16 out)
    gemm_std<0><<<dim3(1, MROWS / MT), 256, SMEMS_SZ>>>(
        pF, pCT, tok_kb, nullptr, nullptr, pZ, KF, 256);
    // x1 = x + transpose(z * lw^T + lb)
    gemm_std<1><<<dim3(T_ / NT, MROWS / MT), 256, SMEMS_SZ>>>(
        pZ, pWT, tok_lb, x, pX1, nullptr, 256, 0);

    // ---- channel mixing ----
    pack_stage<<<(1024 * KF + 512 * 1024 + 255) / 256, 256>>>(
        ch_coef, ch_lw, pCC, pWC, 1024, 512 * 1024);
    feat_ch<<<B_ * T_, 256>>>(pX1, ln2_w, ln2_b, pF);
    // z2 (M x 1024) = F * coef^T + kbias  (fp16 out)
    gemm_std<0><<<dim3(1024 / NT, MROWS / MT), 256, SMEMS_SZ>>>(
        pF, pCC, ch_kb, nullptr, nullptr, pZ, KF, 1024);
    // out = x1 + (z2 * lw^T + lb)
    gemm_std<2><<<dim3(C_ / NT, MROWS / MT), 256, SMEMS_SZ>>>(
        pZ, pWC, ch_lb, pX1, out, nullptr, 1024, 512);
}

// round 9
// speedup vs baseline: 1.9376x; 1.0090x over previous
#include <cuda_runtime.h>
#include <cuda_fp16.h>
#include <math.h>
#include <stdint.h>

#define B_  32
#define T_  512
#define C_  512
#define TD_ 256
#define G_  3
#define MROWS 16384
#define KF  3072               // feature K (single stream)

#define MT 128
#define NT 256
#define BK 64
#define NTHR 512
// fp16 gemm smem: per stage A 16K | B 32K = 48K, 4 stages
#define SOFF_B 16384u
#define SBUF 49152u
#define SMEMS_SZ (4 * 49152)
#define STG_S 261

// ---------------- scratch arena ----------------
#define MB (1024ull * 1024ull)
#define OFF_F     0ull             // features fp16 (16384 x 3072) 96MB (both stages)
#define OFF_Z     (96ull  * MB)    // z fp16: tok 8MB / ch 32MB
#define OFF_CT    (160ull * MB)    // tok coef (256 x 3072) 1.5MB
#define OFF_WT    (162ull * MB)    // tok lw fp16 (512 x 256) 0.25MB
#define OFF_CC    (164ull * MB)    // ch coef (1024 x 3072) 6MB
#define OFF_WC    (172ull * MB)    // ch lw fp16 (512 x 1024) 1MB
#define OFF_LN    (174ull * MB)    // LN1 out fp32 32MB
#define OFF_X1    (206ull * MB)    // x1 fp32 32MB
__device__ __align__(256) char g_scratch[240ull * MB];

// ---------------- PTX helpers ----------------
__device__ __forceinline__ uint32_t smem_u32(const void* p) {
    uint32_t a;
    asm("{ .reg .u64 t; cvta.to.shared.u64 t, %1; cvt.u32.u64 %0, t; }" : "=r"(a) : "l"(p));
    return a;
}
__device__ __forceinline__ void cpasync16(uint32_t dst, const void* src) {
    asm volatile("cp.async.cg.shared.global [%0], [%1], 16;" :: "r"(dst), "l"(src));
}
__device__ __forceinline__ void cp_commit() { asm volatile("cp.async.commit_group;" ::: "memory"); }
__device__ __forceinline__ void cp_wait0()  { asm volatile("cp.async.wait_group 0;" ::: "memory"); }
__device__ __forceinline__ void cp_wait2()  { asm volatile("cp.async.wait_group 2;" ::: "memory"); }
__device__ __forceinline__ void ldsm4(uint32_t addr, uint32_t r[4]) {
    asm volatile("ldmatrix.sync.aligned.m8n8.x4.shared.b16 {%0,%1,%2,%3}, [%4];"
                 : "=r"(r[0]), "=r"(r[1]), "=r"(r[2]), "=r"(r[3]) : "r"(addr));
}
__device__ __forceinline__ void mma_f16(float d[4], const uint32_t a[4], const uint32_t b[2]) {
    asm volatile(
        "mma.sync.aligned.m16n8k16.row.col.f32.f16.f16.f32 "
        "{%0,%1,%2,%3}, {%4,%5,%6,%7}, {%8,%9}, {%0,%1,%2,%3};"
        : "+f"(d[0]), "+f"(d[1]), "+f"(d[2]), "+f"(d[3])
        : "r"(a[0]), "r"(a[1]), "r"(a[2]), "r"(a[3]), "r"(b[0]), "r"(b[1]));
}
// Polynomial sincos, pure FMA pipe, err < 5e-7 for |v| < 30
__device__ __forceinline__ void fast_sincos(float v, float& s, float& c) {
    float k = rintf(v * 0.3183098861837907f);
    float r = fmaf(-k, 3.14159274101257f, v);
    r = fmaf(-k, -8.742277657347586e-8f, r);
    float r2 = r * r;
    float ps = fmaf(r2, -2.5052108385e-8f, 2.7557319224e-6f);
    ps = fmaf(r2, ps, -1.9841269841e-4f);
    ps = fmaf(r2, ps, 8.3333333333e-3f);
    ps = fmaf(r2, ps, -1.6666666667e-1f);
    ps = fmaf(r2, ps, 1.0f);
    float pc = fmaf(r2, -2.7557319224e-7f, 2.4801587302e-5f);
    pc = fmaf(r2, pc, -1.3888888889e-3f);
    pc = fmaf(r2, pc, 4.1666666667e-2f);
    pc = fmaf(r2, pc, -0.5f);
    float sg = (((int)k) & 1) ? -1.0f : 1.0f;
    s = r * ps * sg;
    c = fmaf(r2, pc, 1.0f) * sg;
}

// ---------------- LayerNorm helper (block over one 512-row, 256 thr) --------
__device__ __forceinline__ void ln_row(float2 v, const float* w, const float* b,
                                       float& o0, float& o1) {
    float s  = v.x + v.y;
    float sq = v.x * v.x + v.y * v.y;
    __shared__ float ss[8], sqq[8];
    __shared__ float sm, sr;
    #pragma unroll
    for (int o = 16; o > 0; o >>= 1) {
        s  += __shfl_down_sync(0xffffffffu, s,  o);
        sq += __shfl_down_sync(0xffffffffu, sq, o);
    }
    int lane = threadIdx.x & 31, wid = threadIdx.x >> 5;
    if (lane == 0) { ss[wid] = s; sqq[wid] = sq; }
    __syncthreads();
    if (wid == 0) {
        float a = (lane < 8) ? ss[lane]  : 0.f;
        float q = (lane < 8) ? sqq[lane] : 0.f;
        #pragma unroll
        for (int o = 4; o > 0; o >>= 1) {
            a += __shfl_down_sync(0xffffffffu, a, o);
            q += __shfl_down_sync(0xffffffffu, q, o);
        }
        if (lane == 0) {
            float m = a * (1.0f / 512.f);
            sm = m;
            sr = rsqrtf(q * (1.0f / 512.f) - m * m + 1e-5f);
        }
    }
    __syncthreads();
    float2 wv = ((const float2*)w)[threadIdx.x];
    float2 bv = ((const float2*)b)[threadIdx.x];
    o0 = (v.x - sm) * sr * wv.x + bv.x;
    o1 = (v.y - sm) * sr * wv.y + bv.y;
}

__global__ void ln_kernel(const float* __restrict__ x, const float* __restrict__ w,
                          const float* __restrict__ b, float* __restrict__ out)
{
    int row = blockIdx.x;
    float2 v = ((const float2*)(x + (size_t)row * C_))[threadIdx.x];
    float o0, o1;
    ln_row(v, w, b, o0, o1);
    ((float2*)(out + (size_t)row * C_))[threadIdx.x] = make_float2(o0, o1);
}

// ---- packs: coef (2,O,512,3)->fp16 (O x 3072, k=i*6+g*2+trig); lw -> fp16
__global__ void pack_stage(const float* __restrict__ coef, const float* __restrict__ lw,
                           __half* __restrict__ Cd, __half* __restrict__ Wd,
                           int O, int LWTOT)
{
    int idx = blockIdx.x * blockDim.x + threadIdx.x;
    int nc = O * KF;
    if (idx < nc) {
        int o = idx / KF, r = idx % KF;
        int i = r / 6, rr = r % 6, g = rr >> 1, trig = rr & 1;
        Cd[idx] = __float2half_rn(coef[(((size_t)trig * O + o) * 512 + i) * G_ + g]);
    } else {
        int j = idx - nc;
        if (j < LWTOT) Wd[j] = __float2half_rn(lw[j]);
    }
}

// ---------------- token features (transposed read): fp16 rows ----------------
__global__ __launch_bounds__(256)
void feat_tok(const float* __restrict__ ln, __half* __restrict__ F)
{
    __shared__ float s[256 * 33];
    const int t = threadIdx.x;
    const int c0 = blockIdx.x * 32, i0 = blockIdx.y * 256, b = blockIdx.z;
    #pragma unroll
    for (int it = 0; it < 8; it++) {
        int r = it * 32 + (t >> 3), cc = (t & 7) * 4;
        float4 v = *(const float4*)(ln + ((size_t)(b * T_ + i0 + r)) * C_ + c0 + cc);
        s[r * 33 + cc] = v.x; s[r * 33 + cc + 1] = v.y;
        s[r * 33 + cc + 2] = v.z; s[r * 33 + cc + 3] = v.w;
    }
    __syncthreads();
    const int w = t >> 5, lane = t & 31;
    #pragma unroll
    for (int rep = 0; rep < 4; rep++) {
        const int cl = w * 4 + rep;
        const size_t n = (size_t)(b * C_ + c0 + cl);
        #pragma unroll
        for (int it2 = 0; it2 < 8; it2++) {
            int il = it2 * 32 + lane;
            float v = s[il * 33 + cl];
            float s1, c1;
            fast_sincos(v, s1, c1);
            float c2 = fmaf(2.f * c1, c1, -1.f);
            float s2 = 2.f * s1 * c1;
            float c3 = fmaf(2.f * c1, c2, -c1);
            float s3 = fmaf(2.f * c1, s2, -s1);
            size_t base = n * KF + (size_t)(i0 + il) * 6;
            __half2* p = (__half2*)(F + base);
            p[0] = __floats2half2_rn(c1, s1);
            p[1] = __floats2half2_rn(c2, s2);
            p[2] = __floats2half2_rn(c3, s3);
        }
    }
}

// ---------------- channel features: fused LN2 + expansion -----------------
__global__ __launch_bounds__(256)
void feat_ch(const float* __restrict__ x1, const float* __restrict__ w,
             const float* __restrict__ b, __half* __restrict__ F)
{
    int row = blockIdx.x;
    float2 v = ((const float2*)(x1 + (size_t)row * C_))[threadIdx.x];
    float ln0, ln1;
    ln_row(v, w, b, ln0, ln1);
    #pragma unroll
    for (int q = 0; q < 2; q++) {
        float vv = q ? ln1 : ln0;
        int c = threadIdx.x * 2 + q;
        float s1, c1;
        fast_sincos(vv, s1, c1);
        float c2 = fmaf(2.f * c1, c1, -1.f);
        float s2 = 2.f * s1 * c1;
        float c3 = fmaf(2.f * c1, c2, -c1);
        float s3 = fmaf(2.f * c1, s2, -s1);
        size_t base = (size_t)row * KF + (size_t)c * 6;
        __half2* p = (__half2*)(F + base);
        p[0] = __floats2half2_rn(c1, s1);
        p[1] = __floats2half2_rn(c2, s2);
        p[2] = __floats2half2_rn(c3, s3);
    }
}

// ---- fp16 TN GEMM, 4-stage cp.async, CTA 128x256, 512 thr (16 warps 4x4) ----
// warp tile 32x64. MODE 0: fp16 out outH[m*Ntot+n]=D+bias
// MODE 1: m=(b,c), n=t: outF[(b*T+n)*C+c] = res + D + bias
// MODE 2: outF[m*C+n] = res + D + bias
template<int MODE>
__global__ __launch_bounds__(NTHR, 1)
void gemm_std(const __half* __restrict__ A, const __half* __restrict__ Bm,
              const float* __restrict__ bias, const float* __restrict__ res,
              float* __restrict__ outF, __half* __restrict__ outH,
              int K, int Ntot)
{
    extern __shared__ char smem[];
    const uint32_t sbase = smem_u32(smem);
    const int tid = threadIdx.x, wid = tid >> 5, lane = tid & 31;
    const int m0 = blockIdx.y * MT, n0 = blockIdx.x * NT;
    const int wm = wid >> 2, wn = wid & 3;   // 4x4 warp grid

    float acc[2][8][4];
    #pragma unroll
    for (int i = 0; i < 2; i++)
        #pragma unroll
        for (int j = 0; j < 8; j++)
            #pragma unroll
            for (int q = 0; q < 4; q++) acc[i][j][q] = 0.f;

    const int NC = K >> 6;

    auto load_chunk = [&](int kc, int buf) {
        const uint32_t sb = sbase + (uint32_t)buf * SBUF;
        const size_t kcol = (size_t)kc * BK;
        #pragma unroll
        for (int it = 0; it < 2; it++) {
            int u = tid + it * NTHR;
            int r = u >> 3, cch = u & 7;
            uint32_t off = r * 128 + ((cch ^ (r & 7)) << 4);
            cpasync16(sb + off, (const char*)(A + (size_t)(m0 + r) * K + kcol) + cch * 16);
        }
        #pragma unroll
        for (int it = 0; it < 4; it++) {
            int u = tid + it * NTHR;
            int r = u >> 3, cch = u & 7;
            uint32_t off = r * 128 + ((cch ^ (r & 7)) << 4);
            cpasync16(sb + SOFF_B + off, (const char*)(Bm + (size_t)(n0 + r) * K + kcol) + cch * 16);
        }
    };

    #pragma unroll
    for (int s = 0; s < 3; s++) {
        if (s < NC) load_chunk(s, s);
        cp_commit();
    }

    const int lr = lane & 7, lq = lane >> 3;

    for (int kc = 0; kc < NC; kc++) {
        cp_wait2();
        __syncthreads();
        const uint32_t sb = sbase + (uint32_t)(kc & 3) * SBUF;
        #pragma unroll
        for (int k16 = 0; k16 < 4; k16++) {
            uint32_t ah[2][4];
            #pragma unroll
            for (int i = 0; i < 2; i++) {
                int row = wm * 32 + i * 16 + lr + (lq & 1) * 8;
                int ch  = (k16 * 2 + (lq >> 1)) ^ (row & 7);
                ldsm4(sb + row * 128 + (ch << 4), ah[i]);
            }
            #pragma unroll
            for (int jp = 0; jp < 4; jp++) {
                int row = wn * 64 + jp * 16 + lr + (lq >> 1) * 8;
                int ch  = (k16 * 2 + (lq & 1)) ^ (row & 7);
                uint32_t tb[4];
                ldsm4(sb + SOFF_B + row * 128 + (ch << 4), tb);
                #pragma unroll
                for (int i = 0; i < 2; i++) {
                    mma_f16(acc[i][2*jp],   ah[i], tb);
                    mma_f16(acc[i][2*jp+1], ah[i], tb + 2);
                }
            }
        }
        int nk = kc + 3;
        if (nk < NC) load_chunk(nk, nk & 3);
        cp_commit();
    }
    cp_wait0();
    __syncthreads();

    // stage accumulators to smem
    float* stage = (float*)smem;
    {
        const int g = lane >> 2, t2 = (lane & 3) * 2;
        #pragma unroll
        for (int i = 0; i < 2; i++) {
            int row = wm * 32 + i * 16 + g;
            #pragma unroll
            for (int j = 0; j < 8; j++) {
                int col = wn * 64 + j * 8 + t2;
                stage[row * STG_S + col]           = acc[i][j][0];
                stage[row * STG_S + col + 1]       = acc[i][j][1];
                stage[(row + 8) * STG_S + col]     = acc[i][j][2];
                stage[(row + 8) * STG_S + col + 1] = acc[i][j][3];
            }
        }
    }
    __syncthreads();

    if (MODE == 0) {
        for (int u = tid; u < 128 * (NT / 2); u += NTHR) {
            int r = u >> 7;
            int c = (u & 127) * 2;
            float v0 = stage[r * STG_S + c]     + bias[n0 + c];
            float v1 = stage[r * STG_S + c + 1] + bias[n0 + c + 1];
            size_t rowb = (size_t)(m0 + r) * Ntot;
            ((__half2*)(outH + rowb + n0 + c))[0] = __floats2half2_rn(v0, v1);
        }
    } else if (MODE == 1) {
        const int b = m0 >> 9, c0 = m0 & 511;
        for (int nl = wid; nl < NT; nl += 16) {
            int n = n0 + nl;
            float bn = bias[n];
            size_t obase = ((size_t)(b * T_ + n)) * C_ + c0;
            #pragma unroll
            for (int cc = 0; cc < 4; cc++) {
                int c = lane + cc * 32;
                outF[obase + c] = res[obase + c] + stage[c * STG_S + nl] + bn;
            }
        }
    } else {
        for (int u = tid; u < 128 * (NT / 4); u += NTHR) {
            int r = u >> 6;
            int c = (u & 63) * 4;
            size_t base = (size_t)(m0 + r) * C_ + n0 + c;
            float4 rv = *(const float4*)(res + base);
            float4 ov;
            ov.x = rv.x + stage[r * STG_S + c]     + bias[n0 + c];
            ov.y = rv.y + stage[r * STG_S + c + 1] + bias[n0 + c + 1];
            ov.z = rv.z + stage[r * STG_S + c + 2] + bias[n0 + c + 2];
            ov.w = rv.w + stage[r * STG_S + c + 3] + bias[n0 + c + 3];
            *(float4*)(outF + base) = ov;
        }
    }
}

// ---------------- launch ----------------
extern "C" void kernel_launch(void* const* d_in, const int* in_sizes, int n_in,
                              void* d_out, int out_size)
{
    const float* x        = (const float*)d_in[0];
    const float* ln1_w    = (const float*)d_in[1];
    const float* ln1_b    = (const float*)d_in[2];
    const float* tok_coef = (const float*)d_in[3];
    const float* tok_kb   = (const float*)d_in[4];
    const float* tok_lw   = (const float*)d_in[5];
    const float* tok_lb   = (const float*)d_in[6];
    const float* ln2_w    = (const float*)d_in[7];
    const float* ln2_b    = (const float*)d_in[8];
    const float* ch_coef  = (const float*)d_in[9];
    const float* ch_kb    = (const float*)d_in[10];
    const float* ch_lw    = (const float*)d_in[11];
    const float* ch_lb    = (const float*)d_in[12];
    float* out = (float*)d_out;

    char* base;
    cudaGetSymbolAddress((void**)&base, g_scratch);
    __half* pF  = (__half*)(base + OFF_F);
    __half* pZ  = (__half*)(base + OFF_Z);
    __half* pCT = (__half*)(base + OFF_CT);
    __half* pWT = (__half*)(base + OFF_WT);
    __half* pCC = (__half*)(base + OFF_CC);
    __half* pWC = (__half*)(base + OFF_WC);
    float*  pLn = (float*)(base + OFF_LN);
    float*  pX1 = (float*)(base + OFF_X1);

    cudaFuncSetAttribute(gemm_std<0>, cudaFuncAttributeMaxDynamicSharedMemorySize, SMEMS_SZ);
    cudaFuncSetAttribute(gemm_std<1>, cudaFuncAttributeMaxDynamicSharedMemorySize, SMEMS_SZ);
    cudaFuncSetAttribute(gemm_std<2>, cudaFuncAttributeMaxDynamicSharedMemorySize, SMEMS_SZ);

    // ---- token mixing ----
    ln_kernel<<<B_ * T_, 256>>>(x, ln1_w, ln1_b, pLn);
    pack_stage<<<(TD_ * KF + T_ * TD_ + 255) / 256, 256>>>(
        tok_coef, tok_lw, pCT, pWT, TD_, T_ * TD_);
    feat_tok<<<dim3(C_ / 32, T_ / 256, B_), 256>>>(pLn, pF);
    // z (M x 256) = F * coef^T + kbias  (fp16 out)
    gemm_std<0><<<dim3(1, MROWS / MT), NTHR, SMEMS_SZ>>>(
        pF, pCT, tok_kb, nullptr, nullptr, pZ, KF, 256);
    // x1 = x + transpose(z * lw^T + lb)
    gemm_std<1><<<dim3(T_ / NT, MROWS / MT), NTHR, SMEMS_SZ>>>(
        pZ, pWT, tok_lb, x, pX1, nullptr, 256, 0);

    // ---- channel mixing ----
    pack_stage<<<(1024 * KF + 512 * 1024 + 255) / 256, 256>>>(
        ch_coef, ch_lw, pCC, pWC, 1024, 512 * 1024);
    feat_ch<<<B_ * T_, 256>>>(pX1, ln2_w, ln2_b, pF);
    // z2 (M x 1024) = F * coef^T + kbias  (fp16 out)
    gemm_std<0><<<dim3(1024 / NT, MROWS / MT), NTHR, SMEMS_SZ>>>(
        pF, pCC, ch_kb, nullptr, nullptr, pZ, KF, 1024);
    // out = x1 + (z2 * lw^T + lb)
    gemm_std<2><<<dim3(C_ / NT, MROWS / MT), NTHR, SMEMS_SZ>>>(
        pZ, pWC, ch_lb, pX1, out, nullptr, 1024, 512);
}

// round 11
// speedup vs baseline: 2.2830x; 1.1783x over previous
#include <cuda_runtime.h>
#include <cuda_fp16.h>
#include <math.h>
#include <stdint.h>

#define B_  32
#define T_  512
#define C_  512
#define TD_ 256
#define G_  3
#define MROWS 16384
#define KF  3072               // feature K (single stream)

#define MT 128
#define NT 128
#define BK 64
#define NTHR 256
// fp16 gemm smem: per stage A 16K | B 16K = 32K, 3 stages -> 96KB (2 CTA/SM)
#define SOFF_B 16384u
#define SBUF 32768u
#define SMEMS_SZ (3 * 32768)
#define STG_S 133

// ---------------- scratch arena ----------------
#define MB (1024ull * 1024ull)
#define OFF_F     0ull             // features fp16 (16384 x 3072) 96MB (both stages)
#define OFF_Z     (96ull  * MB)    // z fp16: tok 8MB / ch 32MB
#define OFF_CT    (160ull * MB)    // tok coef (256 x 3072) 1.5MB
#define OFF_WT    (162ull * MB)    // tok lw fp16 (512 x 256) 0.25MB
#define OFF_CC    (164ull * MB)    // ch coef (1024 x 3072) 6MB
#define OFF_WC    (172ull * MB)    // ch lw fp16 (512 x 1024) 1MB
#define OFF_LN    (174ull * MB)    // LN1 out fp32 32MB
#define OFF_X1    (206ull * MB)    // x1 fp32 32MB
__device__ __align__(256) char g_scratch[240ull * MB];

// ---------------- PTX helpers ----------------
__device__ __forceinline__ uint32_t smem_u32(const void* p) {
    uint32_t a;
    asm("{ .reg .u64 t; cvta.to.shared.u64 t, %1; cvt.u32.u64 %0, t; }" : "=r"(a) : "l"(p));
    return a;
}
__device__ __forceinline__ void cpasync16(uint32_t dst, const void* src) {
    asm volatile("cp.async.cg.shared.global [%0], [%1], 16;" :: "r"(dst), "l"(src));
}
__device__ __forceinline__ void cp_commit() { asm volatile("cp.async.commit_group;" ::: "memory"); }
__device__ __forceinline__ void cp_wait0()  { asm volatile("cp.async.wait_group 0;" ::: "memory"); }
__device__ __forceinline__ void cp_wait1()  { asm volatile("cp.async.wait_group 1;" ::: "memory"); }
__device__ __forceinline__ void ldsm4(uint32_t addr, uint32_t r[4]) {
    asm volatile("ldmatrix.sync.aligned.m8n8.x4.shared.b16 {%0,%1,%2,%3}, [%4];"
                 : "=r"(r[0]), "=r"(r[1]), "=r"(r[2]), "=r"(r[3]) : "r"(addr));
}
__device__ __forceinline__ void mma_f16(float d[4], const uint32_t a[4], const uint32_t b[2]) {
    asm volatile(
        "mma.sync.aligned.m16n8k16.row.col.f32.f16.f16.f32 "
        "{%0,%1,%2,%3}, {%4,%5,%6,%7}, {%8,%9}, {%0,%1,%2,%3};"
        : "+f"(d[0]), "+f"(d[1]), "+f"(d[2]), "+f"(d[3])
        : "r"(a[0]), "r"(a[1]), "r"(a[2]), "r"(a[3]), "r"(b[0]), "r"(b[1]));
}
// Polynomial sincos, pure FMA pipe, err < 5e-7 for |v| < 30
__device__ __forceinline__ void fast_sincos(float v, float& s, float& c) {
    float k = rintf(v * 0.3183098861837907f);
    float r = fmaf(-k, 3.14159274101257f, v);
    r = fmaf(-k, -8.742277657347586e-8f, r);
    float r2 = r * r;
    float ps = fmaf(r2, -2.5052108385e-8f, 2.7557319224e-6f);
    ps = fmaf(r2, ps, -1.9841269841e-4f);
    ps = fmaf(r2, ps, 8.3333333333e-3f);
    ps = fmaf(r2, ps, -1.6666666667e-1f);
    ps = fmaf(r2, ps, 1.0f);
    float pc = fmaf(r2, -2.7557319224e-7f, 2.4801587302e-5f);
    pc = fmaf(r2, pc, -1.3888888889e-3f);
    pc = fmaf(r2, pc, 4.1666666667e-2f);
    pc = fmaf(r2, pc, -0.5f);
    float sg = (((int)k) & 1) ? -1.0f : 1.0f;
    s = r * ps * sg;
    c = fmaf(r2, pc, 1.0f) * sg;
}

// ---------------- LayerNorm helper (block over one 512-row, 256 thr) --------
__device__ __forceinline__ void ln_row(float2 v, const float* w, const float* b,
                                       float& o0, float& o1) {
    float s  = v.x + v.y;
    float sq = v.x * v.x + v.y * v.y;
    __shared__ float ss[8], sqq[8];
    __shared__ float sm, sr;
    #pragma unroll
    for (int o = 16; o > 0; o >>= 1) {
        s  += __shfl_down_sync(0xffffffffu, s,  o);
        sq += __shfl_down_sync(0xffffffffu, sq, o);
    }
    int lane = threadIdx.x & 31, wid = threadIdx.x >> 5;
    if (lane == 0) { ss[wid] = s; sqq[wid] = sq; }
    __syncthreads();
    if (wid == 0) {
        float a = (lane < 8) ? ss[lane]  : 0.f;
        float q = (lane < 8) ? sqq[lane] : 0.f;
        #pragma unroll
        for (int o = 4; o > 0; o >>= 1) {
            a += __shfl_down_sync(0xffffffffu, a, o);
            q += __shfl_down_sync(0xffffffffu, q, o);
        }
        if (lane == 0) {
            float m = a * (1.0f / 512.f);
            sm = m;
            sr = rsqrtf(q * (1.0f / 512.f) - m * m + 1e-5f);
        }
    }
    __syncthreads();
    float2 wv = ((const float2*)w)[threadIdx.x];
    float2 bv = ((const float2*)b)[threadIdx.x];
    o0 = (v.x - sm) * sr * wv.x + bv.x;
    o1 = (v.y - sm) * sr * wv.y + bv.y;
}

__global__ void ln_kernel(const float* __restrict__ x, const float* __restrict__ w,
                          const float* __restrict__ b, float* __restrict__ out)
{
    int row = blockIdx.x;
    float2 v = ((const float2*)(x + (size_t)row * C_))[threadIdx.x];
    float o0, o1;
    ln_row(v, w, b, o0, o1);
    ((float2*)(out + (size_t)row * C_))[threadIdx.x] = make_float2(o0, o1);
}

// ---- packs: coef (2,O,512,3)->fp16 (O x 3072, k=i*6+g*2+trig); lw -> fp16
__global__ void pack_stage(const float* __restrict__ coef, const float* __restrict__ lw,
                           __half* __restrict__ Cd, __half* __restrict__ Wd,
                           int O, int LWTOT)
{
    int idx = blockIdx.x * blockDim.x + threadIdx.x;
    int nc = O * KF;
    if (idx < nc) {
        int o = idx / KF, r = idx % KF;
        int i = r / 6, rr = r % 6, g = rr >> 1, trig = rr & 1;
        Cd[idx] = __float2half_rn(coef[(((size_t)trig * O + o) * 512 + i) * G_ + g]);
    } else {
        int j = idx - nc;
        if (j < LWTOT) Wd[j] = __float2half_rn(lw[j]);
    }
}

// ---------------- token features (transposed read): fp16 rows ----------------
__global__ __launch_bounds__(256)
void feat_tok(const float* __restrict__ ln, __half* __restrict__ F)
{
    __shared__ float s[256 * 33];
    const int t = threadIdx.x;
    const int c0 = blockIdx.x * 32, i0 = blockIdx.y * 256, b = blockIdx.z;
    #pragma unroll
    for (int it = 0; it < 8; it++) {
        int r = it * 32 + (t >> 3), cc = (t & 7) * 4;
        float4 v = *(const float4*)(ln + ((size_t)(b * T_ + i0 + r)) * C_ + c0 + cc);
        s[r * 33 + cc] = v.x; s[r * 33 + cc + 1] = v.y;
        s[r * 33 + cc + 2] = v.z; s[r * 33 + cc + 3] = v.w;
    }
    __syncthreads();
    const int w = t >> 5, lane = t & 31;
    #pragma unroll
    for (int rep = 0; rep < 4; rep++) {
        const int cl = w * 4 + rep;
        const size_t n = (size_t)(b * C_ + c0 + cl);
        #pragma unroll
        for (int it2 = 0; it2 < 8; it2++) {
            int il = it2 * 32 + lane;
            float v = s[il * 33 + cl];
            float s1, c1;
            fast_sincos(v, s1, c1);
            float c2 = fmaf(2.f * c1, c1, -1.f);
            float s2 = 2.f * s1 * c1;
            float c3 = fmaf(2.f * c1, c2, -c1);
            float s3 = fmaf(2.f * c1, s2, -s1);
            size_t base = n * KF + (size_t)(i0 + il) * 6;
            __half2* p = (__half2*)(F + base);
            p[0] = __floats2half2_rn(c1, s1);
            p[1] = __floats2half2_rn(c2, s2);
            p[2] = __floats2half2_rn(c3, s3);
        }
    }
}

// ---------------- channel features: fused LN2 + expansion -----------------
__global__ __launch_bounds__(256)
void feat_ch(const float* __restrict__ x1, const float* __restrict__ w,
             const float* __restrict__ b, __half* __restrict__ F)
{
    int row = blockIdx.x;
    float2 v = ((const float2*)(x1 + (size_t)row * C_))[threadIdx.x];
    float ln0, ln1;
    ln_row(v, w, b, ln0, ln1);
    #pragma unroll
    for (int q = 0; q < 2; q++) {
        float vv = q ? ln1 : ln0;
        int c = threadIdx.x * 2 + q;
        float s1, c1;
        fast_sincos(vv, s1, c1);
        float c2 = fmaf(2.f * c1, c1, -1.f);
        float s2 = 2.f * s1 * c1;
        float c3 = fmaf(2.f * c1, c2, -c1);
        float s3 = fmaf(2.f * c1, s2, -s1);
        size_t base = (size_t)row * KF + (size_t)c * 6;
        __half2* p = (__half2*)(F + base);
        p[0] = __floats2half2_rn(c1, s1);
        p[1] = __floats2half2_rn(c2, s2);
        p[2] = __floats2half2_rn(c3, s3);
    }
}

// ---- fp16 TN GEMM, 3-stage cp.async, CTA 128x128, 256 thr, 2 CTAs/SM ----
// 8 warps in 4x2 grid: warp tile 32x64.
// MODE 0: fp16 out outH[m*Ntot+n]=D+bias
// MODE 1: m=(b,c), n=t: outF[(b*T+n)*C+c] = res + D + bias
// MODE 2: outF[m*C+n] = res + D + bias
template<int MODE>
__global__ __launch_bounds__(NTHR, 2)
void gemm_std(const __half* __restrict__ A, const __half* __restrict__ Bm,
              const float* __restrict__ bias, const float* __restrict__ res,
              float* __restrict__ outF, __half* __restrict__ outH,
              int K, int Ntot)
{
    extern __shared__ char smem[];
    const uint32_t sbase = smem_u32(smem);
    const int tid = threadIdx.x, wid = tid >> 5, lane = tid & 31;
    const int m0 = blockIdx.y * MT, n0 = blockIdx.x * NT;
    const int wm = wid >> 1, wn = wid & 1;   // 4x2 warp grid

    float acc[2][8][4];
    #pragma unroll
    for (int i = 0; i < 2; i++)
        #pragma unroll
        for (int j = 0; j < 8; j++)
            #pragma unroll
            for (int q = 0; q < 4; q++) acc[i][j][q] = 0.f;

    const int NC = K >> 6;

    auto load_chunk = [&](int kc, int buf) {
        const uint32_t sb = sbase + (uint32_t)buf * SBUF;
        const size_t kcol = (size_t)kc * BK;
        #pragma unroll
        for (int it = 0; it < 4; it++) {
            int u = tid + it * NTHR;
            int r = u >> 3, cch = u & 7;
            uint32_t off = r * 128 + ((cch ^ (r & 7)) << 4);
            cpasync16(sb + off, (const char*)(A + (size_t)(m0 + r) * K + kcol) + cch * 16);
        }
        #pragma unroll
        for (int it = 0; it < 4; it++) {
            int u = tid + it * NTHR;
            int r = u >> 3, cch = u & 7;
            uint32_t off = r * 128 + ((cch ^ (r & 7)) << 4);
            cpasync16(sb + SOFF_B + off, (const char*)(Bm + (size_t)(n0 + r) * K + kcol) + cch * 16);
        }
    };

    load_chunk(0, 0);
    cp_commit();
    if (NC > 1) load_chunk(1, 1);
    cp_commit();

    const int lr = lane & 7, lq = lane >> 3;

    int cbuf = 0, lbuf = 2;
    for (int kc = 0; kc < NC; kc++) {
        cp_wait1();
        __syncthreads();
        const uint32_t sb = sbase + (uint32_t)cbuf * SBUF;
        #pragma unroll
        for (int k16 = 0; k16 < 4; k16++) {
            uint32_t ah[2][4];
            #pragma unroll
            for (int i = 0; i < 2; i++) {
                int row = wm * 32 + i * 16 + lr + (lq & 1) * 8;
                int ch  = (k16 * 2 + (lq >> 1)) ^ (row & 7);
                ldsm4(sb + row * 128 + (ch << 4), ah[i]);
            }
            #pragma unroll
            for (int jp = 0; jp < 4; jp++) {
                int row = wn * 64 + jp * 16 + lr + (lq >> 1) * 8;
                int ch  = (k16 * 2 + (lq & 1)) ^ (row & 7);
                uint32_t tb[4];
                ldsm4(sb + SOFF_B + row * 128 + (ch << 4), tb);
                #pragma unroll
                for (int i = 0; i < 2; i++) {
                    mma_f16(acc[i][2*jp],   ah[i], tb);
                    mma_f16(acc[i][2*jp+1], ah[i], tb + 2);
                }
            }
        }
        int nk = kc + 2;
        if (nk < NC) load_chunk(nk, lbuf);
        cp_commit();
        cbuf = (cbuf + 1 == 3) ? 0 : cbuf + 1;
        lbuf = (lbuf + 1 == 3) ? 0 : lbuf + 1;
    }
    cp_wait0();
    __syncthreads();

    // stage accumulators to smem
    float* stage = (float*)smem;
    {
        const int g = lane >> 2, t2 = (lane & 3) * 2;
        #pragma unroll
        for (int i = 0; i < 2; i++) {
            int row = wm * 32 + i * 16 + g;
            #pragma unroll
            for (int j = 0; j < 8; j++) {
                int col = wn * 64 + j * 8 + t2;
                stage[row * STG_S + col]           = acc[i][j][0];
                stage[row * STG_S + col + 1]       = acc[i][j][1];
                stage[(row + 8) * STG_S + col]     = acc[i][j][2];
                stage[(row + 8) * STG_S + col + 1] = acc[i][j][3];
            }
        }
    }
    __syncthreads();

    if (MODE == 0) {
        for (int u = tid; u < 128 * (NT / 2); u += NTHR) {
            int r = u >> 6;
            int c = (u & 63) * 2;
            float v0 = stage[r * STG_S + c]     + bias[n0 + c];
            float v1 = stage[r * STG_S + c + 1] + bias[n0 + c + 1];
            size_t rowb = (size_t)(m0 + r) * Ntot;
            ((__half2*)(outH + rowb + n0 + c))[0] = __floats2half2_rn(v0, v1);
        }
    } else if (MODE == 1) {
        const int b = m0 >> 9, c0 = m0 & 511;
        for (int nl = wid; nl < NT; nl += 8) {
            int n = n0 + nl;
            float bn = bias[n];
            size_t obase = ((size_t)(b * T_ + n)) * C_ + c0;
            #pragma unroll
            for (int cc = 0; cc < 4; cc++) {
                int c = lane + cc * 32;
                outF[obase + c] = res[obase + c] + stage[c * STG_S + nl] + bn;
            }
        }
    } else {
        for (int u = tid; u < 128 * (NT / 4); u += NTHR) {
            int r = u >> 5;
            int c = (u & 31) * 4;
            size_t base = (size_t)(m0 + r) * C_ + n0 + c;
            float4 rv = *(const float4*)(res + base);
            float4 ov;
            ov.x = rv.x + stage[r * STG_S + c]     + bias[n0 + c];
            ov.y = rv.y + stage[r * STG_S + c + 1] + bias[n0 + c + 1];
            ov.z = rv.z + stage[r * STG_S + c + 2] + bias[n0 + c + 2];
            ov.w = rv.w + stage[r * STG_S + c + 3] + bias[n0 + c + 3];
            *(float4*)(outF + base) = ov;
        }
    }
}

// ---------------- launch ----------------
extern "C" void kernel_launch(void* const* d_in, const int* in_sizes, int n_in,
                              void* d_out, int out_size)
{
    const float* x        = (const float*)d_in[0];
    const float* ln1_w    = (const float*)d_in[1];
    const float* ln1_b    = (const float*)d_in[2];
    const float* tok_coef = (const float*)d_in[3];
    const float* tok_kb   = (const float*)d_in[4];
    const float* tok_lw   = (const float*)d_in[5];
    const float* tok_lb   = (const float*)d_in[6];
    const float* ln2_w    = (const float*)d_in[7];
    const float* ln2_b    = (const float*)d_in[8];
    const float* ch_coef  = (const float*)d_in[9];
    const float* ch_kb    = (const float*)d_in[10];
    const float* ch_lw    = (const float*)d_in[11];
    const float* ch_lb    = (const float*)d_in[12];
    float* out = (float*)d_out;

    char* base;
    cudaGetSymbolAddress((void**)&base, g_scratch);
    __half* pF  = (__half*)(base + OFF_F);
    __half* pZ  = (__half*)(base + OFF_Z);
    __half* pCT = (__half*)(base + OFF_CT);
    __half* pWT = (__half*)(base + OFF_WT);
    __half* pCC = (__half*)(base + OFF_CC);
    __half* pWC = (__half*)(base + OFF_WC);
    float*  pLn = (float*)(base + OFF_LN);
    float*  pX1 = (float*)(base + OFF_X1);

    cudaFuncSetAttribute(gemm_std<0>, cudaFuncAttributeMaxDynamicSharedMemorySize, SMEMS_SZ);
    cudaFuncSetAttribute(gemm_std<1>, cudaFuncAttributeMaxDynamicSharedMemorySize, SMEMS_SZ);
    cudaFuncSetAttribute(gemm_std<2>, cudaFuncAttributeMaxDynamicSharedMemorySize, SMEMS_SZ);

    // ---- token mixing ----
    ln_kernel<<<B_ * T_, 256>>>(x, ln1_w, ln1_b, pLn);
    pack_stage<<<(TD_ * KF + T_ * TD_ + 255) / 256, 256>>>(
        tok_coef, tok_lw, pCT, pWT, TD_, T_ * TD_);
    feat_tok<<<dim3(C_ / 32, T_ / 256, B_), 256>>>(pLn, pF);
    // z (M x 256) = F * coef^T + kbias  (fp16 out)
    gemm_std<0><<<dim3(TD_ / NT, MROWS / MT), NTHR, SMEMS_SZ>>>(
        pF, pCT, tok_kb, nullptr, nullptr, pZ, KF, 256);
    // x1 = x + transpose(z * lw^T + lb)
    gemm_std<1><<<dim3(T_ / NT, MROWS / MT), NTHR, SMEMS_SZ>>>(
        pZ, pWT, tok_lb, x, pX1, nullptr, 256, 0);

    // ---- channel mixing ----
    pack_stage<<<(1024 * KF + 512 * 1024 + 255) / 256, 256>>>(
        ch_coef, ch_lw, pCC, pWC, 1024, 512 * 1024);
    feat_ch<<<B_ * T_, 256>>>(pX1, ln2_w, ln2_b, pF);
    // z2 (M x 1024) = F * coef^T + kbias  (fp16 out)
    gemm_std<0><<<dim3(1024 / NT, MROWS / MT), NTHR, SMEMS_SZ>>>(
        pF, pCC, ch_kb, nullptr, nullptr, pZ, KF, 1024);
    // out = x1 + (z2 * lw^T + lb)
    gemm_std<2><<<dim3(C_ / NT, MROWS / MT), NTHR, SMEMS_SZ>>>(
        pZ, pWC, ch_lb, pX1, out, nullptr, 1024, 512);
}